// round 3
// baseline (speedup 1.0000x reference)
#include <cuda_runtime.h>

#define BATCH   16
#define NN      400
#define HIDDIM  96
#define DECDIM  64
#define NEDGE   79800
#define NROWS   (BATCH*NN)      /* 6400 */
#define FEATDIM 408
#define ET      128
#define EPSF    1e-8f

typedef unsigned long long ull;

// -------- scratch (device globals: no runtime allocation allowed) --------
__device__ float g_inv[BATCH];
__device__ float g_feats[NROWS*FEATDIM];   // 10.4 MB
__device__ float g_h1[NROWS*HIDDIM];
__device__ float g_h[NROWS*HIDDIM];
__device__ float g_Pa[NROWS*DECDIM];

// -------- packed f32x2 helpers (FFMA2: 2 fp32 FMA per instruction) --------
__device__ __forceinline__ ull pack2(float x, float y) {
    ull r; asm("mov.b64 %0, {%1, %2};" : "=l"(r) : "f"(x), "f"(y)); return r;
}
__device__ __forceinline__ float2 unpack2(ull v) {
    float2 f; asm("mov.b64 {%0, %1}, %2;" : "=f"(f.x), "=f"(f.y) : "l"(v)); return f;
}
__device__ __forceinline__ ull ffma2(ull a, ull b, ull c) {
    ull d; asm("fma.rn.f32x2 %0, %1, %2, %3;" : "=l"(d) : "l"(a), "l"(b), "l"(c)); return d;
}

// -------- kernel 1: per-batch mean of sc_matrix -> inverse denom --------
__global__ void reduce_mean_kernel(const float* __restrict__ sc) {
    __shared__ float red[256];
    int b = blockIdx.x;
    const float* p = sc + (size_t)b * NN * NN;
    float s = 0.f;
    for (int i = threadIdx.x; i < NN*NN; i += 256) s += p[i];
    red[threadIdx.x] = s;
    __syncthreads();
    for (int st = 128; st > 0; st >>= 1) {
        if (threadIdx.x < st) red[threadIdx.x] += red[threadIdx.x + st];
        __syncthreads();
    }
    if (threadIdx.x == 0) {
        float mean = red[0] * (1.f / (float)(NN*NN));
        g_inv[b] = 1.f / fmaxf(mean, EPSF);
    }
}

// -------- kernel 2: materialize feats = [ (nf-mean)/(std+eps) , sc/denom ] --------
__global__ void build_feats_kernel(const float* __restrict__ nf, const float* __restrict__ sc,
                                   const float* __restrict__ smean, const float* __restrict__ sstd) {
    int idx = blockIdx.x * blockDim.x + threadIdx.x;
    if (idx >= NROWS*FEATDIM) return;
    int r = idx / FEATDIM;
    int c = idx - r * FEATDIM;
    float v;
    if (c < 8) v = (nf[r*8 + c] - smean[c]) / (sstd[c] + EPSF);
    else       v = sc[(size_t)r*NN + (c-8)] * g_inv[r / NN];
    g_feats[idx] = v;
}

// -------- kernel 3: generic tiled SGEMM, C = act(A@W + bias) --------
// BM=64, BN=64, BK=8, 256 threads, 4x4 register tile per thread.
__global__ __launch_bounds__(256) void gemm_kernel(
    const float* __restrict__ A, const float* __restrict__ W,
    const float* __restrict__ bias, const float* __restrict__ alphap,
    float* __restrict__ C, int M, int K, int N)
{
    __shared__ float As[8][64];
    __shared__ float Bs[8][64];
    int tid = threadIdx.x;
    int m0 = blockIdx.x * 64;
    int n0 = blockIdx.y * 64;
    int ty = tid >> 4, tx = tid & 15;
    float acc[4][4] = {};
    for (int k0 = 0; k0 < K; k0 += 8) {
        #pragma unroll
        for (int i = tid; i < 512; i += 256) {
            int m = i >> 3, k = i & 7;
            As[k][m] = A[(size_t)(m0 + m) * K + (k0 + k)];
        }
        #pragma unroll
        for (int i = tid; i < 512; i += 256) {
            int k = i >> 6, n = i & 63;
            Bs[k][n] = (n0 + n < N) ? W[(size_t)(k0 + k) * N + (n0 + n)] : 0.f;
        }
        __syncthreads();
        #pragma unroll
        for (int kk = 0; kk < 8; kk++) {
            float4 a  = *(const float4*)&As[kk][ty*4];
            float4 bv = *(const float4*)&Bs[kk][tx*4];
            float av[4] = {a.x, a.y, a.z, a.w};
            float bw[4] = {bv.x, bv.y, bv.z, bv.w};
            #pragma unroll
            for (int i2 = 0; i2 < 4; i2++)
                #pragma unroll
                for (int j2 = 0; j2 < 4; j2++)
                    acc[i2][j2] = fmaf(av[i2], bw[j2], acc[i2][j2]);
        }
        __syncthreads();
    }
    float alpha = alphap ? alphap[0] : 0.f;
    bool act = (alphap != nullptr);
    #pragma unroll
    for (int i2 = 0; i2 < 4; i2++) {
        int row = m0 + ty*4 + i2;
        #pragma unroll
        for (int j2 = 0; j2 < 4; j2++) {
            int col = n0 + tx*4 + j2;
            if (col < N) {
                float v = acc[i2][j2] + (bias ? bias[col] : 0.f);
                if (act) v = (v >= 0.f) ? v : alpha * v;
                C[(size_t)row * N + col] = v;
            }
        }
    }
}

// -------- kernel 4: fused per-edge decoder --------
// u  = Pa_i + Pa_j + |h_i-h_j|@Wb + (h_i*h_j)@Wc + b1 ; z1 = prelu(u)
// z2 = prelu(z1@W2 + b2) ; out = z2 . w3 + b3
// 128 edges/block, 256 threads, thread = 4 edges x 8 channels (f32x2 packed).
#define DEC_SMEM_FLOATS (2*96*ET + 2*96*64 + 64*64 + 3*64)
#define DEC_SMEM_BYTES  (DEC_SMEM_FLOATS*4 + 2*ET*4)

__global__ __launch_bounds__(256, 1) void decoder_kernel(
    const float* __restrict__ h, const float* __restrict__ Pa,
    const float* __restrict__ Wd1, const float* __restrict__ b1,
    const float* __restrict__ a1p, const float* __restrict__ W2,
    const float* __restrict__ b2, const float* __restrict__ a2p,
    const float* __restrict__ W3, const float* __restrict__ b3p,
    const int* __restrict__ ei, const int* __restrict__ ej,
    float* __restrict__ out)
{
    extern __shared__ float smem[];
    float* s_abs = smem;                 // [96][ET]
    float* s_mul = smem + 96*ET;         // [96][ET]
    float* s_wb  = smem + 2*96*ET;       // [96][64]
    float* s_wc  = s_wb + 96*64;         // [96][64]
    float* s_w2  = s_wc + 96*64;         // [64][64]
    float* s_b1  = s_w2 + 64*64;
    float* s_b2  = s_b1 + 64;
    float* s_w3  = s_b2 + 64;
    int*   s_ei  = (int*)(s_w3 + 64);
    int*   s_ej  = s_ei + ET;

    int tid = threadIdx.x;
    int b   = blockIdx.y;
    int e0  = blockIdx.x * ET;

    // stage weights / biases / edge indices
    const float* Wb = Wd1 + 96*64;   // rows 96..191 of W_d1
    const float* Wc = Wd1 + 192*64;  // rows 192..287
    for (int i = tid; i < 96*64; i += 256) { s_wb[i] = Wb[i]; s_wc[i] = Wc[i]; }
    for (int i = tid; i < 64*64; i += 256) s_w2[i] = W2[i];
    if (tid < 64) { s_b1[tid] = b1[tid]; s_b2[tid] = b2[tid]; s_w3[tid] = W3[tid]; }
    if (tid < ET) {
        int e = e0 + tid;
        bool v = (e < NEDGE);
        s_ei[tid] = v ? ei[e] : 0;
        s_ej[tid] = v ? ej[e] : 0;
    }
    float a1 = a1p[0], a2 = a2p[0], b3 = b3p[0];
    __syncthreads();

    // stage |h_i - h_j| and h_i * h_j  (k-major, edge-contiguous)
    {
        int el = tid & (ET-1);
        bool valid = (e0 + el) < NEDGE;
        const float4* h4 = (const float4*)h;
        int bi = (b*NN + s_ei[el]) * 24;   // 96 floats = 24 float4 per node
        int bj = (b*NN + s_ej[el]) * 24;
        for (int q = (tid >> 7); q < 24; q += 2) {
            float4 hi = h4[bi + q];
            float4 hj = h4[bj + q];
            float4 av, mv;
            av.x = fabsf(hi.x - hj.x); mv.x = hi.x * hj.x;
            av.y = fabsf(hi.y - hj.y); mv.y = hi.y * hj.y;
            av.z = fabsf(hi.z - hj.z); mv.z = hi.z * hj.z;
            av.w = fabsf(hi.w - hj.w); mv.w = hi.w * hj.w;
            if (!valid) { av = make_float4(0.f,0.f,0.f,0.f); mv = av; }
            int k = q * 4;
            s_abs[(k+0)*ET + el] = av.x;  s_mul[(k+0)*ET + el] = mv.x;
            s_abs[(k+1)*ET + el] = av.y;  s_mul[(k+1)*ET + el] = mv.y;
            s_abs[(k+2)*ET + el] = av.z;  s_mul[(k+2)*ET + el] = mv.z;
            s_abs[(k+3)*ET + el] = av.w;  s_mul[(k+3)*ET + el] = mv.w;
        }
    }
    __syncthreads();

    int cg = tid & 7;        // channel group: d0 = cg*8
    int eg = tid >> 3;       // edge group:  ebase = eg*4
    int d0 = cg * 8;
    int ebase = eg * 4;

    // ---- main GEMM: u += abs@Wb + mul@Wc (f32x2 packed channel pairs) ----
    ull acc[4][4];
    #pragma unroll
    for (int e = 0; e < 4; e++)
        #pragma unroll
        for (int p = 0; p < 4; p++) acc[e][p] = 0ull;

    #pragma unroll 4
    for (int k = 0; k < 96; k++) {
        float4 a4  = *(const float4*)&s_abs[k*ET + ebase];
        float4 m4  = *(const float4*)&s_mul[k*ET + ebase];
        float4 wb0 = *(const float4*)&s_wb[k*64 + d0];
        float4 wb1 = *(const float4*)&s_wb[k*64 + d0 + 4];
        float4 wc0 = *(const float4*)&s_wc[k*64 + d0];
        float4 wc1 = *(const float4*)&s_wc[k*64 + d0 + 4];
        ull wb[4] = { pack2(wb0.x,wb0.y), pack2(wb0.z,wb0.w), pack2(wb1.x,wb1.y), pack2(wb1.z,wb1.w) };
        ull wc[4] = { pack2(wc0.x,wc0.y), pack2(wc0.z,wc0.w), pack2(wc1.x,wc1.y), pack2(wc1.z,wc1.w) };
        float av[4] = {a4.x,a4.y,a4.z,a4.w};
        float mv[4] = {m4.x,m4.y,m4.z,m4.w};
        #pragma unroll
        for (int e = 0; e < 4; e++) {
            ull ad = pack2(av[e], av[e]);
            ull md = pack2(mv[e], mv[e]);
            #pragma unroll
            for (int p = 0; p < 4; p++) {
                acc[e][p] = ffma2(ad, wb[p], acc[e][p]);
                acc[e][p] = ffma2(md, wc[p], acc[e][p]);
            }
        }
    }
    __syncthreads();   // everyone done reading s_abs/s_mul before reuse

    // ---- u + Pa_i + Pa_j + b1, prelu, store z1 (k-major) into reused smem ----
    float* s_z1 = s_abs;   // [64][ET]
    float zv[4][8];
    float4 bb0 = *(const float4*)&s_b1[d0];
    float4 bb1 = *(const float4*)&s_b1[d0 + 4];
    float bbv[8] = {bb0.x,bb0.y,bb0.z,bb0.w,bb1.x,bb1.y,bb1.z,bb1.w};
    #pragma unroll
    for (int e = 0; e < 4; e++) {
        int el = ebase + e;
        int ii = s_ei[el], jj = s_ej[el];
        const float* pai = Pa + (size_t)(b*NN + ii) * 64 + d0;
        const float* paj = Pa + (size_t)(b*NN + jj) * 64 + d0;
        float4 pi0 = *(const float4*)(pai);
        float4 pi1 = *(const float4*)(pai + 4);
        float4 pj0 = *(const float4*)(paj);
        float4 pj1 = *(const float4*)(paj + 4);
        float pv[8] = {pi0.x+pj0.x, pi0.y+pj0.y, pi0.z+pj0.z, pi0.w+pj0.w,
                       pi1.x+pj1.x, pi1.y+pj1.y, pi1.z+pj1.z, pi1.w+pj1.w};
        #pragma unroll
        for (int p = 0; p < 4; p++) {
            float2 af = unpack2(acc[e][p]);
            float ux = af.x + pv[2*p]   + bbv[2*p];
            float uy = af.y + pv[2*p+1] + bbv[2*p+1];
            zv[e][2*p]   = (ux >= 0.f) ? ux : a1 * ux;
            zv[e][2*p+1] = (uy >= 0.f) ? uy : a1 * uy;
        }
    }
    #pragma unroll
    for (int dd = 0; dd < 8; dd++) {
        float4 st = make_float4(zv[0][dd], zv[1][dd], zv[2][dd], zv[3][dd]);
        *(float4*)&s_z1[(d0 + dd) * ET + ebase] = st;
    }
    __syncthreads();

    // ---- layer d2: z1 @ W2 ----
    ull acc2[4][4];
    #pragma unroll
    for (int e = 0; e < 4; e++)
        #pragma unroll
        for (int p = 0; p < 4; p++) acc2[e][p] = 0ull;

    #pragma unroll 4
    for (int k = 0; k < 64; k++) {
        float4 a4 = *(const float4*)&s_z1[k*ET + ebase];
        float4 w0 = *(const float4*)&s_w2[k*64 + d0];
        float4 w1 = *(const float4*)&s_w2[k*64 + d0 + 4];
        ull w[4] = { pack2(w0.x,w0.y), pack2(w0.z,w0.w), pack2(w1.x,w1.y), pack2(w1.z,w1.w) };
        float av[4] = {a4.x,a4.y,a4.z,a4.w};
        #pragma unroll
        for (int e = 0; e < 4; e++) {
            ull ad = pack2(av[e], av[e]);
            #pragma unroll
            for (int p = 0; p < 4; p++)
                acc2[e][p] = ffma2(ad, w[p], acc2[e][p]);
        }
    }

    // ---- prelu(z2) . w3, reduce across the 8 channel-group lanes ----
    float4 sb0 = *(const float4*)&s_b2[d0];
    float4 sb1 = *(const float4*)&s_b2[d0+4];
    float4 sw0 = *(const float4*)&s_w3[d0];
    float4 sw1 = *(const float4*)&s_w3[d0+4];
    float b2v[8] = {sb0.x,sb0.y,sb0.z,sb0.w,sb1.x,sb1.y,sb1.z,sb1.w};
    float w3v[8] = {sw0.x,sw0.y,sw0.z,sw0.w,sw1.x,sw1.y,sw1.z,sw1.w};
    float part[4];
    #pragma unroll
    for (int e = 0; e < 4; e++) {
        float s = 0.f;
        #pragma unroll
        for (int p = 0; p < 4; p++) {
            float2 z = unpack2(acc2[e][p]);
            float u0 = z.x + b2v[2*p];   u0 = (u0 >= 0.f) ? u0 : a2 * u0;
            float u1 = z.y + b2v[2*p+1]; u1 = (u1 >= 0.f) ? u1 : a2 * u1;
            s = fmaf(u0, w3v[2*p], s);
            s = fmaf(u1, w3v[2*p+1], s);
        }
        part[e] = s;
    }
    #pragma unroll
    for (int e = 0; e < 4; e++) {
        part[e] += __shfl_down_sync(0xffffffffu, part[e], 4, 8);
        part[e] += __shfl_down_sync(0xffffffffu, part[e], 2, 8);
        part[e] += __shfl_down_sync(0xffffffffu, part[e], 1, 8);
    }
    if (cg == 0) {
        #pragma unroll
        for (int e = 0; e < 4; e++) {
            int eglob = e0 + ebase + e;
            if (eglob < NEDGE) out[(size_t)b * NEDGE + eglob] = part[e] + b3;
        }
    }
}

// -------- host launcher --------
extern "C" void kernel_launch(void* const* d_in, const int* in_sizes, int n_in,
                              void* d_out, int out_size) {
    (void)in_sizes; (void)n_in; (void)out_size;
    // metadata order: x, node_features, sc_matrix, static_mean, static_std,
    // W_e1,b_e1,a_e1, W_e2,b_e2,a_e2, W_d1,b_d1,a_d1, W_d2,b_d2,a_d2, W_d3,b_d3, ei, ej
    const float* nf    = (const float*)d_in[1];
    const float* sc    = (const float*)d_in[2];
    const float* smean = (const float*)d_in[3];
    const float* sstd  = (const float*)d_in[4];
    const float* We1   = (const float*)d_in[5];
    const float* be1   = (const float*)d_in[6];
    const float* ae1   = (const float*)d_in[7];
    const float* We2   = (const float*)d_in[8];
    const float* be2   = (const float*)d_in[9];
    const float* ae2   = (const float*)d_in[10];
    const float* Wd1   = (const float*)d_in[11];
    const float* bd1   = (const float*)d_in[12];
    const float* ad1   = (const float*)d_in[13];
    const float* Wd2   = (const float*)d_in[14];
    const float* bd2   = (const float*)d_in[15];
    const float* ad2   = (const float*)d_in[16];
    const float* Wd3   = (const float*)d_in[17];
    const float* bd3   = (const float*)d_in[18];
    const int*   ei    = (const int*)d_in[19];
    const int*   ej    = (const int*)d_in[20];
    float* out = (float*)d_out;

    float *pfeats, *ph1, *ph, *ppa;
    cudaGetSymbolAddress((void**)&pfeats, g_feats);
    cudaGetSymbolAddress((void**)&ph1,   g_h1);
    cudaGetSymbolAddress((void**)&ph,    g_h);
    cudaGetSymbolAddress((void**)&ppa,   g_Pa);

    cudaFuncSetAttribute(decoder_kernel,
                         cudaFuncAttributeMaxDynamicSharedMemorySize, DEC_SMEM_BYTES);

    // 1) per-batch sc mean -> 1/max(mean,eps)
    reduce_mean_kernel<<<BATCH, 256>>>(sc);
    // 2) feats (6400 x 408)
    build_feats_kernel<<<(NROWS*FEATDIM + 255)/256, 256>>>(nf, sc, smean, sstd);
    // 3) h1 = prelu(feats @ W_e1 + b_e1)
    gemm_kernel<<<dim3(NROWS/64, 2), 256>>>(pfeats, We1, be1, ae1, ph1, NROWS, FEATDIM, HIDDIM);
    // 4) h = prelu(h1 @ W_e2 + b_e2)
    gemm_kernel<<<dim3(NROWS/64, 2), 256>>>(ph1, We2, be2, ae2, ph, NROWS, HIDDIM, HIDDIM);
    // 5) Pa = h @ W_d1[0:96,:]   (no bias, no activation)
    gemm_kernel<<<dim3(NROWS/64, 1), 256>>>(ph, Wd1, nullptr, nullptr, ppa, NROWS, HIDDIM, DECDIM);
    // 6) fused decoder over all (batch, edge-tile)
    decoder_kernel<<<dim3((NEDGE + ET - 1)/ET, BATCH), 256, DEC_SMEM_BYTES>>>(
        ph, ppa, Wd1, bd1, ad1, Wd2, bd2, ad2, Wd3, bd3, ei, ej, out);
}

// round 6
// speedup vs baseline: 2.4958x; 2.4958x over previous
#include <cuda_runtime.h>
#include <cuda_bf16.h>
#include <cstdint>

#define BATCH   16
#define NN      400
#define HIDDIM  96
#define DECDIM  64
#define NEDGE   79800
#define NROWS   (BATCH*NN)      /* 6400 */
#define FEATDIM 408
#define EPSF    1e-8f

#define ETD     128             /* edges per tile */
#define NTILE   624             /* ceil(79800/128) */
#define NWORK   (NTILE*BATCH)   /* 9984 */
#define NCTA    148

/* ---- smem layout (bytes). A/W arrays are bf16 with padded k-stride for
   conflict-free fragment loads: k=96 arrays stride 104 bf16 (52 words),
   k=64 arrays stride 72 bf16 (36 words). psum stride 68 fp32. ---- */
#define AKW   52                /* 32-bit words per row, k=96 arrays */
#define ZKW   36                /* 32-bit words per row, k=64 arrays */
#define PSTR  68                /* fp32 per row, psum */

#define OF_ABSH 0               /* 128 x 104 bf16 = 26624 B */
#define OF_ABSL 26624
#define OF_MULH 53248
#define OF_MULL 79872           /* A arrays end 106496 */
#define OF_Z1H  0               /* overlay on abs (after GEMM1) 128x72 bf16 */
#define OF_Z1L  18432
#define OF_PSUM 106496          /* 128 x 68 fp32 = 34816 */
#define OF_RED  106496          /* reuse psum for cross-warp reduce */
#define OF_WBH  141312          /* 64 x 104 bf16 = 13312 */
#define OF_WBL  154624
#define OF_WCH  167936
#define OF_WCL  181248
#define OF_W2H  194560          /* 64 x 72 bf16 = 9216 */
#define OF_W2L  203776
#define OF_B1   212992
#define OF_B2   213248
#define OF_W3   213504
#define OF_EI   213760
#define OF_EJ   214272
#define DEC_SMEM 214784

/* -------- scratch (device globals; no runtime allocation allowed) -------- */
__device__ float g_inv[BATCH];
__device__ float g_feats[NROWS*FEATDIM];
__device__ float g_h1[NROWS*HIDDIM];
__device__ float g_h[NROWS*HIDDIM];
__device__ float g_Pa[NROWS*DECDIM];

/* ======================= helpers ======================= */
/* split two fp32 into packed bf16x2 hi and lo words (lo = exact residual) */
__device__ __forceinline__ void split2(float x0, float x1, uint32_t& hi, uint32_t& lo) {
    asm("cvt.rn.bf16x2.f32 %0, %1, %2;" : "=r"(hi) : "f"(x1), "f"(x0)); /* lo16=x0 hi16=x1 */
    float h0 = __uint_as_float(hi << 16);
    float h1 = __uint_as_float(hi & 0xffff0000u);
    float l0 = x0 - h0, l1 = x1 - h1;
    asm("cvt.rn.bf16x2.f32 %0, %1, %2;" : "=r"(lo) : "f"(l1), "f"(l0));
}

__device__ __forceinline__ void mma_bf16(float* c, const uint32_t* a, const uint32_t* b) {
    asm volatile("mma.sync.aligned.m16n8k16.row.col.f32.bf16.bf16.f32 "
                 "{%0,%1,%2,%3}, {%4,%5,%6,%7}, {%8,%9}, {%0,%1,%2,%3};"
                 : "+f"(c[0]), "+f"(c[1]), "+f"(c[2]), "+f"(c[3])
                 : "r"(a[0]), "r"(a[1]), "r"(a[2]), "r"(a[3]), "r"(b[0]), "r"(b[1]));
}

/* ======================= encoder kernels ======================= */
__global__ void reduce_mean_kernel(const float* __restrict__ sc) {
    __shared__ float red[256];
    int b = blockIdx.x;
    const float* p = sc + (size_t)b * NN * NN;
    float s = 0.f;
    for (int i = threadIdx.x; i < NN*NN; i += 256) s += p[i];
    red[threadIdx.x] = s;
    __syncthreads();
    for (int st = 128; st > 0; st >>= 1) {
        if (threadIdx.x < st) red[threadIdx.x] += red[threadIdx.x + st];
        __syncthreads();
    }
    if (threadIdx.x == 0) g_inv[b] = 1.f / fmaxf(red[0] * (1.f/(float)(NN*NN)), EPSF);
}

__global__ void build_feats_kernel(const float* __restrict__ nf, const float* __restrict__ sc,
                                   const float* __restrict__ smean, const float* __restrict__ sstd) {
    int idx = blockIdx.x * blockDim.x + threadIdx.x;
    if (idx >= NROWS*FEATDIM) return;
    int r = idx / FEATDIM;
    int c = idx - r * FEATDIM;
    float v;
    if (c < 8) v = (nf[r*8 + c] - smean[c]) / (sstd[c] + EPSF);
    else       v = sc[(size_t)r*NN + (c-8)] * g_inv[r / NN];
    g_feats[idx] = v;
}

__global__ __launch_bounds__(256) void gemm_kernel(
    const float* __restrict__ A, const float* __restrict__ W,
    const float* __restrict__ bias, const float* __restrict__ alphap,
    float* __restrict__ C, int M, int K, int N)
{
    __shared__ float As[8][64];
    __shared__ float Bs[8][64];
    int tid = threadIdx.x;
    int m0 = blockIdx.x * 64, n0 = blockIdx.y * 64;
    int ty = tid >> 4, tx = tid & 15;
    float acc[4][4] = {};
    for (int k0 = 0; k0 < K; k0 += 8) {
        #pragma unroll
        for (int i = tid; i < 512; i += 256) {
            int m = i >> 3, k = i & 7;
            As[k][m] = A[(size_t)(m0 + m) * K + (k0 + k)];
        }
        #pragma unroll
        for (int i = tid; i < 512; i += 256) {
            int k = i >> 6, n = i & 63;
            Bs[k][n] = (n0 + n < N) ? W[(size_t)(k0 + k) * N + (n0 + n)] : 0.f;
        }
        __syncthreads();
        #pragma unroll
        for (int kk = 0; kk < 8; kk++) {
            float4 a  = *(const float4*)&As[kk][ty*4];
            float4 bv = *(const float4*)&Bs[kk][tx*4];
            float av[4] = {a.x, a.y, a.z, a.w};
            float bw[4] = {bv.x, bv.y, bv.z, bv.w};
            #pragma unroll
            for (int i2 = 0; i2 < 4; i2++)
                #pragma unroll
                for (int j2 = 0; j2 < 4; j2++)
                    acc[i2][j2] = fmaf(av[i2], bw[j2], acc[i2][j2]);
        }
        __syncthreads();
    }
    float alpha = alphap ? alphap[0] : 0.f;
    bool act = (alphap != nullptr);
    #pragma unroll
    for (int i2 = 0; i2 < 4; i2++) {
        int row = m0 + ty*4 + i2;
        #pragma unroll
        for (int j2 = 0; j2 < 4; j2++) {
            int col = n0 + tx*4 + j2;
            if (col < N) {
                float v = acc[i2][j2] + (bias ? bias[col] : 0.f);
                if (act) v = (v >= 0.f) ? v : alpha * v;
                C[(size_t)row * N + col] = v;
            }
        }
    }
}

/* ======================= mma.sync bf16x3 persistent decoder ======================= */
__global__ __launch_bounds__(256, 1)
void decoder_mma_kernel(
    const float* __restrict__ h, const float* __restrict__ Pa,
    const float* __restrict__ Wd1, const float* __restrict__ b1,
    const float* __restrict__ a1p, const float* __restrict__ W2,
    const float* __restrict__ b2, const float* __restrict__ a2p,
    const float* __restrict__ W3, const float* __restrict__ b3p,
    const int* __restrict__ ei, const int* __restrict__ ej,
    float* __restrict__ out)
{
    extern __shared__ char sm[];
    int tid  = threadIdx.x;
    int wid  = tid >> 5;
    int lane = tid & 31;
    int g    = lane >> 2;      /* row group 0..7 */
    int t    = lane & 3;       /* thread-in-group */
    int mblk  = (wid & 3) * 32;
    int nhalf = (wid >> 2) * 32;

    /* ---- stage split weights once ---- */
    for (int idx = tid; idx < 64*96; idx += 256) {
        int n = idx / 96, k = idx - n * 96;
        float vb = Wd1[(96  + k)*64 + n];
        float vc = Wd1[(192 + k)*64 + n];
        __nv_bfloat16 bh = __float2bfloat16_rn(vb);
        __nv_bfloat16 bl = __float2bfloat16_rn(vb - __bfloat162float(bh));
        __nv_bfloat16 ch = __float2bfloat16_rn(vc);
        __nv_bfloat16 cl = __float2bfloat16_rn(vc - __bfloat162float(ch));
        int o = n * 104 + k;
        ((__nv_bfloat16*)(sm + OF_WBH))[o] = bh;
        ((__nv_bfloat16*)(sm + OF_WBL))[o] = bl;
        ((__nv_bfloat16*)(sm + OF_WCH))[o] = ch;
        ((__nv_bfloat16*)(sm + OF_WCL))[o] = cl;
    }
    for (int idx = tid; idx < 64*64; idx += 256) {
        int n = idx >> 6, k = idx & 63;
        float v = W2[k*64 + n];
        __nv_bfloat16 vh = __float2bfloat16_rn(v);
        __nv_bfloat16 vl = __float2bfloat16_rn(v - __bfloat162float(vh));
        int o = n * 72 + k;
        ((__nv_bfloat16*)(sm + OF_W2H))[o] = vh;
        ((__nv_bfloat16*)(sm + OF_W2L))[o] = vl;
    }
    if (tid < 64) {
        ((float*)(sm + OF_B1))[tid] = b1[tid];
        ((float*)(sm + OF_B2))[tid] = b2[tid];
        ((float*)(sm + OF_W3))[tid] = W3[tid];
    }
    float a1 = a1p[0], a2 = a2p[0], b3 = b3p[0];
    __syncthreads();

    const int* s_ei = (const int*)(sm + OF_EI);
    const int* s_ej = (const int*)(sm + OF_EJ);

    for (int work = blockIdx.x; work < NWORK; work += NCTA) {
        int b  = work / NTILE;
        int tt = work - b * NTILE;
        int e0 = tt * ETD;

        /* ---- edge indices ---- */
        if (tid < ETD) {
            int e = e0 + tid;
            bool v = (e < NEDGE);
            ((int*)(sm + OF_EI))[tid] = v ? ei[e] : 0;
            ((int*)(sm + OF_EJ))[tid] = v ? ej[e] : 0;
        }
        __syncthreads();   /* also fences previous tile's red reads vs psum writes */

        /* ---- stage abs/mul (hi/lo bf16) + psum = Pa_i + Pa_j ---- */
        {
            int el = tid >> 1, half = tid & 1;
            int ii = s_ei[el], jj = s_ej[el];
            const float4* hi4 = (const float4*)(h + ((size_t)b*NN + ii) * 96) + half*12;
            const float4* hj4 = (const float4*)(h + ((size_t)b*NN + jj) * 96) + half*12;
            #pragma unroll
            for (int q = 0; q < 12; q++) {
                float4 x = hi4[q], y = hj4[q];
                float a0 = fabsf(x.x - y.x), A1 = fabsf(x.y - y.y);
                float a2v = fabsf(x.z - y.z), a3 = fabsf(x.w - y.w);
                float m0 = x.x*y.x, m1 = x.y*y.y, m2 = x.z*y.z, m3 = x.w*y.w;
                uint32_t ah0, al0, ah1, al1, mh0, ml0, mh1, ml1;
                split2(a0, A1, ah0, al0);  split2(a2v, a3, ah1, al1);
                split2(m0, m1, mh0, ml0);  split2(m2, m3, mh1, ml1);
                int w = el*AKW + half*24 + q*2;
                *(uint2*)(sm + OF_ABSH + (size_t)w*4) = make_uint2(ah0, ah1);
                *(uint2*)(sm + OF_ABSL + (size_t)w*4) = make_uint2(al0, al1);
                *(uint2*)(sm + OF_MULH + (size_t)w*4) = make_uint2(mh0, mh1);
                *(uint2*)(sm + OF_MULL + (size_t)w*4) = make_uint2(ml0, ml1);
            }
            const float4* pi4 = (const float4*)(Pa + ((size_t)b*NN + ii) * 64) + half*8;
            const float4* pj4 = (const float4*)(Pa + ((size_t)b*NN + jj) * 64) + half*8;
            #pragma unroll
            for (int q = 0; q < 8; q++) {
                float4 p = pi4[q], r = pj4[q];
                float4 s4 = make_float4(p.x+r.x, p.y+r.y, p.z+r.z, p.w+r.w);
                *(float4*)(sm + OF_PSUM + (size_t)(el*PSTR + half*32 + q*4)*4) = s4;
            }
        }
        __syncthreads();

        /* ---- GEMM1: C1 = abs@Wb + mul@Wc (bf16x3, fp32 acc) ---- */
        float acc[2][4][4];
        #pragma unroll
        for (int mt = 0; mt < 2; mt++)
            #pragma unroll
            for (int nt = 0; nt < 4; nt++)
                #pragma unroll
                for (int c = 0; c < 4; c++) acc[mt][nt][c] = 0.f;

        #pragma unroll
        for (int kc = 0; kc < 6; kc++) {
            uint32_t Af[2][4][4];   /* [mt][absh,absl,mulh,mull][frag] */
            int wb = kc*8 + t;
            #pragma unroll
            for (int mt = 0; mt < 2; mt++) {
                int r0 = mblk + mt*16 + g;
                const uint32_t* p0 = (const uint32_t*)(sm + OF_ABSH);
                const uint32_t* p1 = (const uint32_t*)(sm + OF_ABSL);
                const uint32_t* p2 = (const uint32_t*)(sm + OF_MULH);
                const uint32_t* p3 = (const uint32_t*)(sm + OF_MULL);
                int o0 = r0*AKW + wb, o1 = (r0+8)*AKW + wb;
                Af[mt][0][0]=p0[o0]; Af[mt][0][1]=p0[o1]; Af[mt][0][2]=p0[o0+4]; Af[mt][0][3]=p0[o1+4];
                Af[mt][1][0]=p1[o0]; Af[mt][1][1]=p1[o1]; Af[mt][1][2]=p1[o0+4]; Af[mt][1][3]=p1[o1+4];
                Af[mt][2][0]=p2[o0]; Af[mt][2][1]=p2[o1]; Af[mt][2][2]=p2[o0+4]; Af[mt][2][3]=p2[o1+4];
                Af[mt][3][0]=p3[o0]; Af[mt][3][1]=p3[o1]; Af[mt][3][2]=p3[o0+4]; Af[mt][3][3]=p3[o1+4];
            }
            #pragma unroll
            for (int nt = 0; nt < 4; nt++) {
                int rb = (nhalf + nt*8 + g)*AKW + wb;
                const uint32_t* qbh = (const uint32_t*)(sm + OF_WBH);
                const uint32_t* qbl = (const uint32_t*)(sm + OF_WBL);
                const uint32_t* qch = (const uint32_t*)(sm + OF_WCH);
                const uint32_t* qcl = (const uint32_t*)(sm + OF_WCL);
                uint32_t Bbh[2] = { qbh[rb], qbh[rb+4] };
                uint32_t Bbl[2] = { qbl[rb], qbl[rb+4] };
                uint32_t Bch[2] = { qch[rb], qch[rb+4] };
                uint32_t Bcl[2] = { qcl[rb], qcl[rb+4] };
                #pragma unroll
                for (int mt = 0; mt < 2; mt++) {
                    float* c = acc[mt][nt];
                    mma_bf16(c, Af[mt][0], Bbh);
                    mma_bf16(c, Af[mt][0], Bbl);
                    mma_bf16(c, Af[mt][1], Bbh);
                    mma_bf16(c, Af[mt][2], Bch);
                    mma_bf16(c, Af[mt][2], Bcl);
                    mma_bf16(c, Af[mt][3], Bch);
                }
            }
        }
        __syncthreads();   /* all GEMM1 smem reads done before z1 overwrites abs */

        /* ---- epilogue 1: z1 = prelu(C1 + psum + b1) -> hi/lo bf16 smem ---- */
        {
            const float* sb1 = (const float*)(sm + OF_B1);
            #pragma unroll
            for (int mt = 0; mt < 2; mt++) {
                int r = mblk + mt*16 + g;
                #pragma unroll
                for (int nt = 0; nt < 4; nt++) {
                    int c = nhalf + nt*8 + 2*t;
                    float2 p0 = *(const float2*)(sm + OF_PSUM + (size_t)(r*PSTR + c)*4);
                    float2 p1 = *(const float2*)(sm + OF_PSUM + (size_t)((r+8)*PSTR + c)*4);
                    float bc0 = sb1[c], bc1 = sb1[c+1];
                    float u00 = acc[mt][nt][0] + p0.x + bc0; u00 = (u00 >= 0.f) ? u00 : a1*u00;
                    float u01 = acc[mt][nt][1] + p0.y + bc1; u01 = (u01 >= 0.f) ? u01 : a1*u01;
                    float u10 = acc[mt][nt][2] + p1.x + bc0; u10 = (u10 >= 0.f) ? u10 : a1*u10;
                    float u11 = acc[mt][nt][3] + p1.y + bc1; u11 = (u11 >= 0.f) ? u11 : a1*u11;
                    uint32_t h0, l0, h1, l1;
                    split2(u00, u01, h0, l0);
                    split2(u10, u11, h1, l1);
                    int w0 = r*ZKW + (c >> 1), w1 = (r+8)*ZKW + (c >> 1);
                    *(uint32_t*)(sm + OF_Z1H + (size_t)w0*4) = h0;
                    *(uint32_t*)(sm + OF_Z1L + (size_t)w0*4) = l0;
                    *(uint32_t*)(sm + OF_Z1H + (size_t)w1*4) = h1;
                    *(uint32_t*)(sm + OF_Z1L + (size_t)w1*4) = l1;
                }
            }
        }
        __syncthreads();

        /* ---- GEMM2: C2 = z1 @ W2 (bf16x3) ---- */
        float acc2[2][4][4];
        #pragma unroll
        for (int mt = 0; mt < 2; mt++)
            #pragma unroll
            for (int nt = 0; nt < 4; nt++)
                #pragma unroll
                for (int c = 0; c < 4; c++) acc2[mt][nt][c] = 0.f;

        #pragma unroll
        for (int kc = 0; kc < 4; kc++) {
            uint32_t Zf[2][2][4];
            int wb = kc*8 + t;
            #pragma unroll
            for (int mt = 0; mt < 2; mt++) {
                int r0 = mblk + mt*16 + g;
                const uint32_t* ph = (const uint32_t*)(sm + OF_Z1H);
                const uint32_t* pl = (const uint32_t*)(sm + OF_Z1L);
                int o0 = r0*ZKW + wb, o1 = (r0+8)*ZKW + wb;
                Zf[mt][0][0]=ph[o0]; Zf[mt][0][1]=ph[o1]; Zf[mt][0][2]=ph[o0+4]; Zf[mt][0][3]=ph[o1+4];
                Zf[mt][1][0]=pl[o0]; Zf[mt][1][1]=pl[o1]; Zf[mt][1][2]=pl[o0+4]; Zf[mt][1][3]=pl[o1+4];
            }
            #pragma unroll
            for (int nt = 0; nt < 4; nt++) {
                int rb = (nhalf + nt*8 + g)*ZKW + wb;
                const uint32_t* qh = (const uint32_t*)(sm + OF_W2H);
                const uint32_t* ql = (const uint32_t*)(sm + OF_W2L);
                uint32_t Bh[2] = { qh[rb], qh[rb+4] };
                uint32_t Bl[2] = { ql[rb], ql[rb+4] };
                #pragma unroll
                for (int mt = 0; mt < 2; mt++) {
                    float* c = acc2[mt][nt];
                    mma_bf16(c, Zf[mt][0], Bh);
                    mma_bf16(c, Zf[mt][0], Bl);
                    mma_bf16(c, Zf[mt][1], Bh);
                }
            }
        }

        /* ---- epilogue 2: dot(prelu(C2 + b2), w3), reduce, store ---- */
        {
            const float* sb2 = (const float*)(sm + OF_B2);
            const float* sw3 = (const float*)(sm + OF_W3);
            float pr[2][2] = {{0.f,0.f},{0.f,0.f}};
            #pragma unroll
            for (int mt = 0; mt < 2; mt++) {
                #pragma unroll
                for (int nt = 0; nt < 4; nt++) {
                    int c = nhalf + nt*8 + 2*t;
                    float bc0 = sb2[c], bc1 = sb2[c+1];
                    float w0 = sw3[c],  w1 = sw3[c+1];
                    float u00 = acc2[mt][nt][0] + bc0; u00 = (u00 >= 0.f) ? u00 : a2*u00;
                    float u01 = acc2[mt][nt][1] + bc1; u01 = (u01 >= 0.f) ? u01 : a2*u01;
                    float u10 = acc2[mt][nt][2] + bc0; u10 = (u10 >= 0.f) ? u10 : a2*u10;
                    float u11 = acc2[mt][nt][3] + bc1; u11 = (u11 >= 0.f) ? u11 : a2*u11;
                    pr[mt][0] = fmaf(u00, w0, fmaf(u01, w1, pr[mt][0]));
                    pr[mt][1] = fmaf(u10, w0, fmaf(u11, w1, pr[mt][1]));
                }
            }
            #pragma unroll
            for (int mt = 0; mt < 2; mt++) {
                #pragma unroll
                for (int rr = 0; rr < 2; rr++) {
                    pr[mt][rr] += __shfl_xor_sync(0xffffffffu, pr[mt][rr], 1);
                    pr[mt][rr] += __shfl_xor_sync(0xffffffffu, pr[mt][rr], 2);
                }
            }
            if (t == 0) {
                float* red = (float*)(sm + OF_RED);
                int nh = wid >> 2;
                #pragma unroll
                for (int mt = 0; mt < 2; mt++) {
                    int r = mblk + mt*16 + g;
                    red[r*2 + nh]     = pr[mt][0];
                    red[(r+8)*2 + nh] = pr[mt][1];
                }
            }
        }
        __syncthreads();
        if (tid < ETD) {
            const float* red = (const float*)(sm + OF_RED);
            int eg = e0 + tid;
            if (eg < NEDGE)
                out[(size_t)b * NEDGE + eg] = red[tid*2] + red[tid*2 + 1] + b3;
        }
        /* next-iteration top syncthreads fences red reads vs psum re-staging */
    }
}

/* ======================= host launcher ======================= */
extern "C" void kernel_launch(void* const* d_in, const int* in_sizes, int n_in,
                              void* d_out, int out_size) {
    (void)in_sizes; (void)n_in; (void)out_size;
    const float* nf    = (const float*)d_in[1];
    const float* sc    = (const float*)d_in[2];
    const float* smean = (const float*)d_in[3];
    const float* sstd  = (const float*)d_in[4];
    const float* We1   = (const float*)d_in[5];
    const float* be1   = (const float*)d_in[6];
    const float* ae1   = (const float*)d_in[7];
    const float* We2   = (const float*)d_in[8];
    const float* be2   = (const float*)d_in[9];
    const float* ae2   = (const float*)d_in[10];
    const float* Wd1   = (const float*)d_in[11];
    const float* bd1   = (const float*)d_in[12];
    const float* ad1   = (const float*)d_in[13];
    const float* Wd2   = (const float*)d_in[14];
    const float* bd2   = (const float*)d_in[15];
    const float* ad2   = (const float*)d_in[16];
    const float* Wd3   = (const float*)d_in[17];
    const float* bd3   = (const float*)d_in[18];
    const int*   ei    = (const int*)d_in[19];
    const int*   ej    = (const int*)d_in[20];
    float* out = (float*)d_out;

    float *pfeats, *ph1, *ph, *ppa;
    cudaGetSymbolAddress((void**)&pfeats, g_feats);
    cudaGetSymbolAddress((void**)&ph1,   g_h1);
    cudaGetSymbolAddress((void**)&ph,    g_h);
    cudaGetSymbolAddress((void**)&ppa,   g_Pa);

    cudaFuncSetAttribute(decoder_mma_kernel,
                         cudaFuncAttributeMaxDynamicSharedMemorySize, DEC_SMEM);

    reduce_mean_kernel<<<BATCH, 256>>>(sc);
    build_feats_kernel<<<(NROWS*FEATDIM + 255)/256, 256>>>(nf, sc, smean, sstd);
    gemm_kernel<<<dim3(NROWS/64, 2), 256>>>(pfeats, We1, be1, ae1, ph1, NROWS, FEATDIM, HIDDIM);
    gemm_kernel<<<dim3(NROWS/64, 2), 256>>>(ph1, We2, be2, ae2, ph, NROWS, HIDDIM, HIDDIM);
    gemm_kernel<<<dim3(NROWS/64, 1), 256>>>(ph, Wd1, nullptr, nullptr, ppa, NROWS, HIDDIM, DECDIM);
    decoder_mma_kernel<<<NCTA, 256, DEC_SMEM>>>(
        ph, ppa, Wd1, bd1, ad1, Wd2, bd2, ad2, Wd3, bd3, ei, ej, out);
}

// round 7
// speedup vs baseline: 3.1646x; 1.2680x over previous
#include <cuda_runtime.h>
#include <cuda_fp16.h>
#include <cstdint>

#define BATCH   16
#define NN      400
#define HIDDIM  96
#define DECDIM  64
#define NEDGE   79800
#define NROWS   (BATCH*NN)      /* 6400 */
#define FEATDIM 408
#define EPSF    1e-8f

#define ETD     128             /* edges per tile */
#define NTILE   624             /* ceil(79800/128) */
#define NWORK   (NTILE*BATCH)   /* 9984 */
#define NCTA    148

/* ---- strides: k=96 arrays padded to 104 halves (208B row, 52 words);
   k=64 arrays padded to 72 halves (144B row, 36 words); psum 68 fp32/row.
   208B stride: banks cycle 20*g mod 32 (full perm); 144B: 4*g mod 32 (full perm). */
#define AKW   52
#define ZKW   36
#define PSTR  68

/* ---- smem byte offsets ---- */
#define OF_ABSH 0               /* 128x104 f16 = 26624 */
#define OF_MULH 26624
#define OF_PSUM 53248           /* 128x68 f32 = 34816 */
#define OF_WBH  88064           /* 64x104 f16 = 13312 each */
#define OF_WBL  101376
#define OF_WCH  114688
#define OF_WCL  128000
#define OF_W2H  141312          /* 64x72 f16 = 9216 each */
#define OF_W2L  150528
#define OF_B1   159744
#define OF_B2   160000
#define OF_W3   160256
#define OF_Z1H  160512          /* 128x72 f16 = 18432 each */
#define OF_Z1L  178944
#define OF_RED  197376          /* 128x2 f32 = 1024 */
#define DEC_SMEM 198400

/* -------- scratch (device globals; no runtime allocation allowed) -------- */
__device__ float g_inv[BATCH];
__device__ float g_feats[NROWS*FEATDIM];
__device__ float g_h1[NROWS*HIDDIM];
__device__ float g_h[NROWS*HIDDIM];
__device__ float g_Pa[NROWS*DECDIM];

/* ======================= helpers ======================= */
__device__ __forceinline__ uint32_t smem_u32(const void* p) {
    uint32_t a;
    asm("{ .reg .u64 t; cvta.to.shared.u64 t, %1; cvt.u32.u64 %0, t; }" : "=r"(a) : "l"(p));
    return a;
}
__device__ __forceinline__ uint32_t packh2(float x0, float x1) {
    __half2 hh = __floats2half2_rn(x0, x1);
    return *reinterpret_cast<uint32_t*>(&hh);
}
__device__ __forceinline__ void splith(float x0, float x1, uint32_t& hi, uint32_t& lo) {
    __half2 hh = __floats2half2_rn(x0, x1);
    float l0 = x0 - __half2float(__low2half(hh));
    float l1 = x1 - __half2float(__high2half(hh));
    __half2 ll = __floats2half2_rn(l0, l1);
    hi = *reinterpret_cast<uint32_t*>(&hh);
    lo = *reinterpret_cast<uint32_t*>(&ll);
}
__device__ __forceinline__ void ldsm4(uint32_t* r, uint32_t a) {
    asm volatile("ldmatrix.sync.aligned.m8n8.x4.shared.b16 {%0,%1,%2,%3}, [%4];"
                 : "=r"(r[0]), "=r"(r[1]), "=r"(r[2]), "=r"(r[3]) : "r"(a));
}
__device__ __forceinline__ void mma_f16(float* c, const uint32_t* a, uint32_t b0, uint32_t b1) {
    asm volatile("mma.sync.aligned.m16n8k16.row.col.f32.f16.f16.f32 "
                 "{%0,%1,%2,%3}, {%4,%5,%6,%7}, {%8,%9}, {%0,%1,%2,%3};"
                 : "+f"(c[0]), "+f"(c[1]), "+f"(c[2]), "+f"(c[3])
                 : "r"(a[0]), "r"(a[1]), "r"(a[2]), "r"(a[3]), "r"(b0), "r"(b1));
}

/* ======================= encoder kernels ======================= */
__global__ void reduce_mean_kernel(const float* __restrict__ sc) {
    __shared__ float red[256];
    int b = blockIdx.x;
    const float* p = sc + (size_t)b * NN * NN;
    float s = 0.f;
    for (int i = threadIdx.x; i < NN*NN; i += 256) s += p[i];
    red[threadIdx.x] = s;
    __syncthreads();
    for (int st = 128; st > 0; st >>= 1) {
        if (threadIdx.x < st) red[threadIdx.x] += red[threadIdx.x + st];
        __syncthreads();
    }
    if (threadIdx.x == 0) g_inv[b] = 1.f / fmaxf(red[0] * (1.f/(float)(NN*NN)), EPSF);
}

__global__ void build_feats_kernel(const float* __restrict__ nf, const float* __restrict__ sc,
                                   const float* __restrict__ smean, const float* __restrict__ sstd) {
    int idx = blockIdx.x * blockDim.x + threadIdx.x;
    if (idx >= NROWS*FEATDIM) return;
    int r = idx / FEATDIM;
    int c = idx - r * FEATDIM;
    float v;
    if (c < 8) v = (nf[r*8 + c] - smean[c]) / (sstd[c] + EPSF);
    else       v = sc[(size_t)r*NN + (c-8)] * g_inv[r / NN];
    g_feats[idx] = v;
}

__global__ __launch_bounds__(256) void gemm_kernel(
    const float* __restrict__ A, const float* __restrict__ W,
    const float* __restrict__ bias, const float* __restrict__ alphap,
    float* __restrict__ C, int M, int K, int N)
{
    __shared__ float As[8][64];
    __shared__ float Bs[8][64];
    int tid = threadIdx.x;
    int m0 = blockIdx.x * 64, n0 = blockIdx.y * 64;
    int ty = tid >> 4, tx = tid & 15;
    float acc[4][4] = {};
    for (int k0 = 0; k0 < K; k0 += 8) {
        #pragma unroll
        for (int i = tid; i < 512; i += 256) {
            int m = i >> 3, k = i & 7;
            As[k][m] = A[(size_t)(m0 + m) * K + (k0 + k)];
        }
        #pragma unroll
        for (int i = tid; i < 512; i += 256) {
            int k = i >> 6, n = i & 63;
            Bs[k][n] = (n0 + n < N) ? W[(size_t)(k0 + k) * N + (n0 + n)] : 0.f;
        }
        __syncthreads();
        #pragma unroll
        for (int kk = 0; kk < 8; kk++) {
            float4 a  = *(const float4*)&As[kk][ty*4];
            float4 bv = *(const float4*)&Bs[kk][tx*4];
            float av[4] = {a.x, a.y, a.z, a.w};
            float bw[4] = {bv.x, bv.y, bv.z, bv.w};
            #pragma unroll
            for (int i2 = 0; i2 < 4; i2++)
                #pragma unroll
                for (int j2 = 0; j2 < 4; j2++)
                    acc[i2][j2] = fmaf(av[i2], bw[j2], acc[i2][j2]);
        }
        __syncthreads();
    }
    float alpha = alphap ? alphap[0] : 0.f;
    bool act = (alphap != nullptr);
    #pragma unroll
    for (int i2 = 0; i2 < 4; i2++) {
        int row = m0 + ty*4 + i2;
        #pragma unroll
        for (int j2 = 0; j2 < 4; j2++) {
            int col = n0 + tx*4 + j2;
            if (col < N) {
                float v = acc[i2][j2] + (bias ? bias[col] : 0.f);
                if (act) v = (v >= 0.f) ? v : alpha * v;
                C[(size_t)row * N + col] = v;
            }
        }
    }
}

/* ======================= fp16 mma.sync persistent decoder ======================= */
__global__ __launch_bounds__(256, 1)
void decoder_mma_kernel(
    const float* __restrict__ h, const float* __restrict__ Pa,
    const float* __restrict__ Wd1, const float* __restrict__ b1,
    const float* __restrict__ a1p, const float* __restrict__ W2,
    const float* __restrict__ b2, const float* __restrict__ a2p,
    const float* __restrict__ W3, const float* __restrict__ b3p,
    const int* __restrict__ ei, const int* __restrict__ ej,
    float* __restrict__ out)
{
    extern __shared__ char sm[];
    uint32_t smb = smem_u32(sm);
    int tid  = threadIdx.x;
    int wid  = tid >> 5;
    int lane = tid & 31;
    int g    = lane >> 2;
    int t    = lane & 3;
    int mblk  = (wid & 3) * 32;
    int nhalf = (wid >> 2) * 32;

    /* ---- stage weights once: Wb/Wc 2-term fp16 [n][k] stride 104h; W2 2-term stride 72h ---- */
    for (int idx = tid; idx < 64*96; idx += 256) {
        int n = idx / 96, k = idx - n * 96;
        float vb = Wd1[(96  + k)*64 + n];
        float vc = Wd1[(192 + k)*64 + n];
        __half bh = __float2half_rn(vb);
        __half bl = __float2half_rn(vb - __half2float(bh));
        __half ch = __float2half_rn(vc);
        __half cl = __float2half_rn(vc - __half2float(ch));
        int o = n * 104 + k;
        ((__half*)(sm + OF_WBH))[o] = bh;
        ((__half*)(sm + OF_WBL))[o] = bl;
        ((__half*)(sm + OF_WCH))[o] = ch;
        ((__half*)(sm + OF_WCL))[o] = cl;
    }
    for (int idx = tid; idx < 64*64; idx += 256) {
        int n = idx >> 6, k = idx & 63;
        float v = W2[k*64 + n];
        __half vh = __float2half_rn(v);
        __half vl = __float2half_rn(v - __half2float(vh));
        int o = n * 72 + k;
        ((__half*)(sm + OF_W2H))[o] = vh;
        ((__half*)(sm + OF_W2L))[o] = vl;
    }
    if (tid < 64) {
        ((float*)(sm + OF_B1))[tid] = b1[tid];
        ((float*)(sm + OF_B2))[tid] = b2[tid];
        ((float*)(sm + OF_W3))[tid] = W3[tid];
    }
    float a1 = a1p[0], a2 = a2p[0], b3 = b3p[0];
    __syncthreads();

    /* per-warp ldmatrix lane address components */
    uint32_t laneA  = (uint32_t)((lane & 15)*208 + (lane >> 4)*16);
    uint32_t laneB  = (uint32_t)(((lane >> 4)*8 + (lane & 7))*208 + ((lane >> 3) & 1)*16);
    uint32_t laneAz = (uint32_t)((lane & 15)*144 + (lane >> 4)*16);
    uint32_t laneBz = (uint32_t)(((lane >> 4)*8 + (lane & 7))*144 + ((lane >> 3) & 1)*16);

    uint32_t aAbs = smb + OF_ABSH + mblk*208 + laneA;
    uint32_t aMul = smb + OF_MULH + mblk*208 + laneA;
    uint32_t bWbh = smb + OF_WBH + nhalf*208 + laneB;
    uint32_t bWbl = smb + OF_WBL + nhalf*208 + laneB;
    uint32_t bWch = smb + OF_WCH + nhalf*208 + laneB;
    uint32_t bWcl = smb + OF_WCL + nhalf*208 + laneB;
    uint32_t aZh  = smb + OF_Z1H + mblk*144 + laneAz;
    uint32_t aZl  = smb + OF_Z1L + mblk*144 + laneAz;
    uint32_t bW2h = smb + OF_W2H + nhalf*144 + laneBz;
    uint32_t bW2l = smb + OF_W2L + nhalf*144 + laneBz;

    for (int work = blockIdx.x; work < NWORK; work += NCTA) {
        int b  = work / NTILE;
        int tt = work - b * NTILE;
        int e0 = tt * ETD;

        /* ---- stage: abs/mul (single fp16) + psum = Pa_i + Pa_j ---- */
        {
            int el = tid >> 1, half = tid & 1;
            int e = e0 + el; if (e >= NEDGE) e = NEDGE - 1;
            int ii = ei[e], jj = ej[e];
            const float4* hi4 = (const float4*)(h + ((size_t)b*NN + ii) * 96) + half*12;
            const float4* hj4 = (const float4*)(h + ((size_t)b*NN + jj) * 96) + half*12;
            #pragma unroll
            for (int q = 0; q < 12; q++) {
                float4 x = hi4[q], y = hj4[q];
                float a0 = fabsf(x.x - y.x), A1 = fabsf(x.y - y.y);
                float a2v = fabsf(x.z - y.z), a3 = fabsf(x.w - y.w);
                uint2 aw = make_uint2(packh2(a0, A1), packh2(a2v, a3));
                uint2 mw = make_uint2(packh2(x.x*y.x, x.y*y.y), packh2(x.z*y.z, x.w*y.w));
                int w = el*AKW + half*24 + q*2;
                *(uint2*)(sm + OF_ABSH + (size_t)w*4) = aw;
                *(uint2*)(sm + OF_MULH + (size_t)w*4) = mw;
            }
            const float4* pi4 = (const float4*)(Pa + ((size_t)b*NN + ii) * 64) + half*8;
            const float4* pj4 = (const float4*)(Pa + ((size_t)b*NN + jj) * 64) + half*8;
            #pragma unroll
            for (int q = 0; q < 8; q++) {
                float4 p = pi4[q], r = pj4[q];
                *(float4*)(sm + OF_PSUM + (size_t)(el*PSTR + half*32 + q*4)*4) =
                    make_float4(p.x+r.x, p.y+r.y, p.z+r.z, p.w+r.w);
            }
        }
        __syncthreads();

        /* ---- GEMM1: C1 = abs@(Wbh+Wbl) + mul@(Wch+Wcl) ---- */
        float acc[2][4][4];
        #pragma unroll
        for (int mt = 0; mt < 2; mt++)
            #pragma unroll
            for (int nt = 0; nt < 4; nt++)
                #pragma unroll
                for (int c = 0; c < 4; c++) acc[mt][nt][c] = 0.f;

        #pragma unroll
        for (int kc = 0; kc < 6; kc++) {
            uint32_t kb = kc * 32;
            uint32_t Aa[2][4], Am[2][4];
            ldsm4(Aa[0], aAbs + kb);
            ldsm4(Aa[1], aAbs + 16*208 + kb);
            ldsm4(Am[0], aMul + kb);
            ldsm4(Am[1], aMul + 16*208 + kb);
            uint32_t Bbh[2][4], Bbl[2][4], Bch[2][4], Bcl[2][4];
            #pragma unroll
            for (int p = 0; p < 2; p++) {
                ldsm4(Bbh[p], bWbh + p*16*208 + kb);
                ldsm4(Bbl[p], bWbl + p*16*208 + kb);
                ldsm4(Bch[p], bWch + p*16*208 + kb);
                ldsm4(Bcl[p], bWcl + p*16*208 + kb);
            }
            #pragma unroll
            for (int nt = 0; nt < 4; nt++) {
                int p = nt >> 1, q = (nt & 1) * 2;
                #pragma unroll
                for (int mt = 0; mt < 2; mt++) {
                    float* c = acc[mt][nt];
                    mma_f16(c, Aa[mt], Bbh[p][q], Bbh[p][q+1]);
                    mma_f16(c, Aa[mt], Bbl[p][q], Bbl[p][q+1]);
                    mma_f16(c, Am[mt], Bch[p][q], Bch[p][q+1]);
                    mma_f16(c, Am[mt], Bcl[p][q], Bcl[p][q+1]);
                }
            }
        }

        /* ---- epilogue 1: z1 = prelu(C1 + psum + b1) -> 2-term fp16 (separate region) ---- */
        {
            const float* sb1 = (const float*)(sm + OF_B1);
            #pragma unroll
            for (int mt = 0; mt < 2; mt++) {
                int r = mblk + mt*16 + g;
                #pragma unroll
                for (int nt = 0; nt < 4; nt++) {
                    int c = nhalf + nt*8 + 2*t;
                    float2 p0 = *(const float2*)(sm + OF_PSUM + (size_t)(r*PSTR + c)*4);
                    float2 p1 = *(const float2*)(sm + OF_PSUM + (size_t)((r+8)*PSTR + c)*4);
                    float bc0 = sb1[c], bc1 = sb1[c+1];
                    float u00 = acc[mt][nt][0] + p0.x + bc0; u00 = (u00 >= 0.f) ? u00 : a1*u00;
                    float u01 = acc[mt][nt][1] + p0.y + bc1; u01 = (u01 >= 0.f) ? u01 : a1*u01;
                    float u10 = acc[mt][nt][2] + p1.x + bc0; u10 = (u10 >= 0.f) ? u10 : a1*u10;
                    float u11 = acc[mt][nt][3] + p1.y + bc1; u11 = (u11 >= 0.f) ? u11 : a1*u11;
                    uint32_t h0, l0, h1, l1;
                    splith(u00, u01, h0, l0);
                    splith(u10, u11, h1, l1);
                    int w0 = r*ZKW + (c >> 1), w1 = (r+8)*ZKW + (c >> 1);
                    *(uint32_t*)(sm + OF_Z1H + (size_t)w0*4) = h0;
                    *(uint32_t*)(sm + OF_Z1L + (size_t)w0*4) = l0;
                    *(uint32_t*)(sm + OF_Z1H + (size_t)w1*4) = h1;
                    *(uint32_t*)(sm + OF_Z1L + (size_t)w1*4) = l1;
                }
            }
        }
        __syncthreads();

        /* ---- GEMM2: C2 = (zh+zl) @ (W2h+W2l), 3-term ---- */
        float acc2[2][4][4];
        #pragma unroll
        for (int mt = 0; mt < 2; mt++)
            #pragma unroll
            for (int nt = 0; nt < 4; nt++)
                #pragma unroll
                for (int c = 0; c < 4; c++) acc2[mt][nt][c] = 0.f;

        #pragma unroll
        for (int kc = 0; kc < 4; kc++) {
            uint32_t kb = kc * 32;
            uint32_t Zh[2][4], Zl[2][4];
            ldsm4(Zh[0], aZh + kb);
            ldsm4(Zh[1], aZh + 16*144 + kb);
            ldsm4(Zl[0], aZl + kb);
            ldsm4(Zl[1], aZl + 16*144 + kb);
            uint32_t B2h[2][4], B2l[2][4];
            #pragma unroll
            for (int p = 0; p < 2; p++) {
                ldsm4(B2h[p], bW2h + p*16*144 + kb);
                ldsm4(B2l[p], bW2l + p*16*144 + kb);
            }
            #pragma unroll
            for (int nt = 0; nt < 4; nt++) {
                int p = nt >> 1, q = (nt & 1) * 2;
                #pragma unroll
                for (int mt = 0; mt < 2; mt++) {
                    float* c = acc2[mt][nt];
                    mma_f16(c, Zh[mt], B2h[p][q], B2h[p][q+1]);
                    mma_f16(c, Zh[mt], B2l[p][q], B2l[p][q+1]);
                    mma_f16(c, Zl[mt], B2h[p][q], B2h[p][q+1]);
                }
            }
        }

        /* ---- epilogue 2: dot(prelu(C2 + b2), w3) -> red ---- */
        {
            const float* sb2 = (const float*)(sm + OF_B2);
            const float* sw3 = (const float*)(sm + OF_W3);
            float pr[2][2] = {{0.f,0.f},{0.f,0.f}};
            #pragma unroll
            for (int mt = 0; mt < 2; mt++) {
                #pragma unroll
                for (int nt = 0; nt < 4; nt++) {
                    int c = nhalf + nt*8 + 2*t;
                    float bc0 = sb2[c], bc1 = sb2[c+1];
                    float w0 = sw3[c],  w1 = sw3[c+1];
                    float u00 = acc2[mt][nt][0] + bc0; u00 = (u00 >= 0.f) ? u00 : a2*u00;
                    float u01 = acc2[mt][nt][1] + bc1; u01 = (u01 >= 0.f) ? u01 : a2*u01;
                    float u10 = acc2[mt][nt][2] + bc0; u10 = (u10 >= 0.f) ? u10 : a2*u10;
                    float u11 = acc2[mt][nt][3] + bc1; u11 = (u11 >= 0.f) ? u11 : a2*u11;
                    pr[mt][0] = fmaf(u00, w0, fmaf(u01, w1, pr[mt][0]));
                    pr[mt][1] = fmaf(u10, w0, fmaf(u11, w1, pr[mt][1]));
                }
            }
            #pragma unroll
            for (int mt = 0; mt < 2; mt++) {
                #pragma unroll
                for (int rr = 0; rr < 2; rr++) {
                    pr[mt][rr] += __shfl_xor_sync(0xffffffffu, pr[mt][rr], 1);
                    pr[mt][rr] += __shfl_xor_sync(0xffffffffu, pr[mt][rr], 2);
                }
            }
            if (t == 0) {
                float* red = (float*)(sm + OF_RED);
                int nh = wid >> 2;
                #pragma unroll
                for (int mt = 0; mt < 2; mt++) {
                    int r = mblk + mt*16 + g;
                    red[r*2 + nh]     = pr[mt][0];
                    red[(r+8)*2 + nh] = pr[mt][1];
                }
            }
        }
        __syncthreads();

        /* ---- out ---- */
        if (tid < ETD) {
            const float* red = (const float*)(sm + OF_RED);
            int eg = e0 + tid;
            if (eg < NEDGE)
                out[(size_t)b * NEDGE + eg] = red[tid*2] + red[tid*2 + 1] + b3;
        }
        /* no sync needed: next staging touches absh/mulh/psum only (disjoint from red/z1);
           cross-phase ordering is covered by the stage-end sync of the next tile */
    }
}

/* ======================= host launcher ======================= */
extern "C" void kernel_launch(void* const* d_in, const int* in_sizes, int n_in,
                              void* d_out, int out_size) {
    (void)in_sizes; (void)n_in; (void)out_size;
    const float* nf    = (const float*)d_in[1];
    const float* sc    = (const float*)d_in[2];
    const float* smean = (const float*)d_in[3];
    const float* sstd  = (const float*)d_in[4];
    const float* We1   = (const float*)d_in[5];
    const float* be1   = (const float*)d_in[6];
    const float* ae1   = (const float*)d_in[7];
    const float* We2   = (const float*)d_in[8];
    const float* be2   = (const float*)d_in[9];
    const float* ae2   = (const float*)d_in[10];
    const float* Wd1   = (const float*)d_in[11];
    const float* bd1   = (const float*)d_in[12];
    const float* ad1   = (const float*)d_in[13];
    const float* Wd2   = (const float*)d_in[14];
    const float* bd2   = (const float*)d_in[15];
    const float* ad2   = (const float*)d_in[16];
    const float* Wd3   = (const float*)d_in[17];
    const float* bd3   = (const float*)d_in[18];
    const int*   ei    = (const int*)d_in[19];
    const int*   ej    = (const int*)d_in[20];
    float* out = (float*)d_out;

    float *pfeats, *ph1, *ph, *ppa;
    cudaGetSymbolAddress((void**)&pfeats, g_feats);
    cudaGetSymbolAddress((void**)&ph1,   g_h1);
    cudaGetSymbolAddress((void**)&ph,    g_h);
    cudaGetSymbolAddress((void**)&ppa,   g_Pa);

    cudaFuncSetAttribute(decoder_mma_kernel,
                         cudaFuncAttributeMaxDynamicSharedMemorySize, DEC_SMEM);

    reduce_mean_kernel<<<BATCH, 256>>>(sc);
    build_feats_kernel<<<(NROWS*FEATDIM + 255)/256, 256>>>(nf, sc, smean, sstd);
    gemm_kernel<<<dim3(NROWS/64, 2), 256>>>(pfeats, We1, be1, ae1, ph1, NROWS, FEATDIM, HIDDIM);
    gemm_kernel<<<dim3(NROWS/64, 2), 256>>>(ph1, We2, be2, ae2, ph, NROWS, HIDDIM, HIDDIM);
    gemm_kernel<<<dim3(NROWS/64, 1), 256>>>(ph, Wd1, nullptr, nullptr, ppa, NROWS, HIDDIM, DECDIM);
    decoder_mma_kernel<<<NCTA, 256, DEC_SMEM>>>(
        ph, ppa, Wd1, bd1, ad1, Wd2, bd2, ad2, Wd3, bd3, ei, ej, out);
}

// round 8
// speedup vs baseline: 3.8287x; 1.2099x over previous
#include <cuda_runtime.h>
#include <cuda_fp16.h>
#include <cstdint>

#define BATCH   16
#define NN      400
#define HIDDIM  96
#define DECDIM  64
#define NEDGE   79800
#define NROWS   (BATCH*NN)      /* 6400 */
#define FEATDIM 408
#define EPSF    1e-8f

#define ETD     128             /* edges per tile */
#define NTILE   624             /* ceil(79800/128) */
#define NWORK   (NTILE*BATCH)   /* 9984 */
#define NCTA    148

/* strides: k=96 arrays padded to 104 halves (208B row, 52 words, conflict-free
   ldmatrix perm 20*g mod 32); k=64 arrays 72 halves (144B, perm 4*g); psum 68 f32. */
#define AKW   52
#define ZKW   36
#define PSTR  68

/* ---- smem byte offsets ---- */
#define OF_ABSH 0               /* 128x104 f16 = 26624 */
#define OF_MULH 26624
#define OF_PSUM 53248           /* 128x68 f32 = 34816 */
#define OF_WBH  88064           /* 64x104 f16 = 13312 */
#define OF_WCH  101376
#define OF_W2H  114688          /* 64x72 f16 = 9216 */
#define OF_B1   123904
#define OF_B2   124160
#define OF_W3   124416
#define OF_Z1H  124672          /* 128x72 f16 = 18432 */
#define OF_RED  143104          /* 128x2 f32 = 1024 */
#define DEC_SMEM 144128

/* -------- scratch (device globals; no runtime allocation allowed) -------- */
__device__ float g_inv[BATCH];
__device__ float g_feats[NROWS*FEATDIM];
__device__ float g_h1[NROWS*HIDDIM];
__device__ float g_h[NROWS*HIDDIM];
__device__ float g_Pa[NROWS*DECDIM];

/* ======================= helpers ======================= */
__device__ __forceinline__ uint32_t smem_u32(const void* p) {
    uint32_t a;
    asm("{ .reg .u64 t; cvta.to.shared.u64 t, %1; cvt.u32.u64 %0, t; }" : "=r"(a) : "l"(p));
    return a;
}
__device__ __forceinline__ uint32_t packh2(float x0, float x1) {
    __half2 hh = __floats2half2_rn(x0, x1);
    return *reinterpret_cast<uint32_t*>(&hh);
}
__device__ __forceinline__ void ldsm4(uint32_t* r, uint32_t a) {
    asm volatile("ldmatrix.sync.aligned.m8n8.x4.shared.b16 {%0,%1,%2,%3}, [%4];"
                 : "=r"(r[0]), "=r"(r[1]), "=r"(r[2]), "=r"(r[3]) : "r"(a));
}
__device__ __forceinline__ void mma_f16(float* c, const uint32_t* a, uint32_t b0, uint32_t b1) {
    asm volatile("mma.sync.aligned.m16n8k16.row.col.f32.f16.f16.f32 "
                 "{%0,%1,%2,%3}, {%4,%5,%6,%7}, {%8,%9}, {%0,%1,%2,%3};"
                 : "+f"(c[0]), "+f"(c[1]), "+f"(c[2]), "+f"(c[3])
                 : "r"(a[0]), "r"(a[1]), "r"(a[2]), "r"(a[3]), "r"(b0), "r"(b1));
}

/* ======================= encoder kernels ======================= */
__global__ void reduce_mean_kernel(const float* __restrict__ sc) {
    __shared__ float red[256];
    int b = blockIdx.x;
    const float* p = sc + (size_t)b * NN * NN;
    float s = 0.f;
    for (int i = threadIdx.x; i < NN*NN; i += 256) s += p[i];
    red[threadIdx.x] = s;
    __syncthreads();
    for (int st = 128; st > 0; st >>= 1) {
        if (threadIdx.x < st) red[threadIdx.x] += red[threadIdx.x + st];
        __syncthreads();
    }
    if (threadIdx.x == 0) g_inv[b] = 1.f / fmaxf(red[0] * (1.f/(float)(NN*NN)), EPSF);
}

__global__ void build_feats_kernel(const float* __restrict__ nf, const float* __restrict__ sc,
                                   const float* __restrict__ smean, const float* __restrict__ sstd) {
    int idx = blockIdx.x * blockDim.x + threadIdx.x;
    if (idx >= NROWS*FEATDIM) return;
    int r = idx / FEATDIM;
    int c = idx - r * FEATDIM;
    float v;
    if (c < 8) v = (nf[r*8 + c] - smean[c]) / (sstd[c] + EPSF);
    else       v = sc[(size_t)r*NN + (c-8)] * g_inv[r / NN];
    g_feats[idx] = v;
}

__global__ __launch_bounds__(256) void gemm_kernel(
    const float* __restrict__ A, const float* __restrict__ W,
    const float* __restrict__ bias, const float* __restrict__ alphap,
    float* __restrict__ C, int M, int K, int N)
{
    __shared__ float As[8][64];
    __shared__ float Bs[8][64];
    int tid = threadIdx.x;
    int m0 = blockIdx.x * 64, n0 = blockIdx.y * 64;
    int ty = tid >> 4, tx = tid & 15;
    float acc[4][4] = {};
    for (int k0 = 0; k0 < K; k0 += 8) {
        #pragma unroll
        for (int i = tid; i < 512; i += 256) {
            int m = i >> 3, k = i & 7;
            As[k][m] = A[(size_t)(m0 + m) * K + (k0 + k)];
        }
        #pragma unroll
        for (int i = tid; i < 512; i += 256) {
            int k = i >> 6, n = i & 63;
            Bs[k][n] = (n0 + n < N) ? W[(size_t)(k0 + k) * N + (n0 + n)] : 0.f;
        }
        __syncthreads();
        #pragma unroll
        for (int kk = 0; kk < 8; kk++) {
            float4 a  = *(const float4*)&As[kk][ty*4];
            float4 bv = *(const float4*)&Bs[kk][tx*4];
            float av[4] = {a.x, a.y, a.z, a.w};
            float bw[4] = {bv.x, bv.y, bv.z, bv.w};
            #pragma unroll
            for (int i2 = 0; i2 < 4; i2++)
                #pragma unroll
                for (int j2 = 0; j2 < 4; j2++)
                    acc[i2][j2] = fmaf(av[i2], bw[j2], acc[i2][j2]);
        }
        __syncthreads();
    }
    float alpha = alphap ? alphap[0] : 0.f;
    bool act = (alphap != nullptr);
    #pragma unroll
    for (int i2 = 0; i2 < 4; i2++) {
        int row = m0 + ty*4 + i2;
        #pragma unroll
        for (int j2 = 0; j2 < 4; j2++) {
            int col = n0 + tx*4 + j2;
            if (col < N) {
                float v = acc[i2][j2] + (bias ? bias[col] : 0.f);
                if (act) v = (v >= 0.f) ? v : alpha * v;
                C[(size_t)row * N + col] = v;
            }
        }
    }
}

/* ======================= fp16 mma.sync persistent decoder ======================= */
__global__ __launch_bounds__(256, 1)
void decoder_mma_kernel(
    const float* __restrict__ h, const float* __restrict__ Pa,
    const float* __restrict__ Wd1, const float* __restrict__ b1,
    const float* __restrict__ a1p, const float* __restrict__ W2,
    const float* __restrict__ b2, const float* __restrict__ a2p,
    const float* __restrict__ W3, const float* __restrict__ b3p,
    const int* __restrict__ ei, const int* __restrict__ ej,
    float* __restrict__ out)
{
    extern __shared__ char sm[];
    uint32_t smb = smem_u32(sm);
    int tid  = threadIdx.x;
    int wid  = tid >> 5;
    int lane = tid & 31;
    int g    = lane >> 2;
    int t    = lane & 3;
    int mblk  = (wid & 3) * 32;
    int nhalf = (wid >> 2) * 32;

    /* ---- stage weights once (single fp16, [n][k]) ---- */
    for (int idx = tid; idx < 64*96; idx += 256) {
        int n = idx / 96, k = idx - n * 96;
        int o = n * 104 + k;
        ((__half*)(sm + OF_WBH))[o] = __float2half_rn(Wd1[(96  + k)*64 + n]);
        ((__half*)(sm + OF_WCH))[o] = __float2half_rn(Wd1[(192 + k)*64 + n]);
    }
    for (int idx = tid; idx < 64*64; idx += 256) {
        int n = idx >> 6, k = idx & 63;
        ((__half*)(sm + OF_W2H))[n * 72 + k] = __float2half_rn(W2[k*64 + n]);
    }
    if (tid < 64) {
        ((float*)(sm + OF_B1))[tid] = b1[tid];
        ((float*)(sm + OF_B2))[tid] = b2[tid];
        ((float*)(sm + OF_W3))[tid] = W3[tid];
    }
    float a1 = a1p[0], a2 = a2p[0], b3 = b3p[0];
    __syncthreads();

    /* per-warp ldmatrix lane address components */
    uint32_t laneA  = (uint32_t)((lane & 15)*208 + (lane >> 4)*16);
    uint32_t laneB  = (uint32_t)(((lane >> 4)*8 + (lane & 7))*208 + ((lane >> 3) & 1)*16);
    uint32_t laneAz = (uint32_t)((lane & 15)*144 + (lane >> 4)*16);
    uint32_t laneBz = (uint32_t)(((lane >> 4)*8 + (lane & 7))*144 + ((lane >> 3) & 1)*16);

    uint32_t aAbs = smb + OF_ABSH + mblk*208 + laneA;
    uint32_t aMul = smb + OF_MULH + mblk*208 + laneA;
    uint32_t bWbh = smb + OF_WBH + nhalf*208 + laneB;
    uint32_t bWch = smb + OF_WCH + nhalf*208 + laneB;
    uint32_t aZh  = smb + OF_Z1H + mblk*144 + laneAz;
    uint32_t bW2h = smb + OF_W2H + nhalf*144 + laneBz;

    for (int work = blockIdx.x; work < NWORK; work += NCTA) {
        int b  = work / NTILE;
        int tt = work - b * NTILE;
        int e0 = tt * ETD;

        /* ---- stage: abs/mul fp16 + psum = Pa_i + Pa_j ---- */
        {
            int el = tid >> 1, half = tid & 1;
            int e = e0 + el; if (e >= NEDGE) e = NEDGE - 1;
            int ii = ei[e], jj = ej[e];
            const float4* hi4 = (const float4*)(h + ((size_t)b*NN + ii) * 96) + half*12;
            const float4* hj4 = (const float4*)(h + ((size_t)b*NN + jj) * 96) + half*12;
            #pragma unroll
            for (int q = 0; q < 12; q++) {
                float4 x = hi4[q], y = hj4[q];
                uint2 aw = make_uint2(packh2(fabsf(x.x - y.x), fabsf(x.y - y.y)),
                                      packh2(fabsf(x.z - y.z), fabsf(x.w - y.w)));
                uint2 mw = make_uint2(packh2(x.x*y.x, x.y*y.y), packh2(x.z*y.z, x.w*y.w));
                int w = el*AKW + half*24 + q*2;
                *(uint2*)(sm + OF_ABSH + (size_t)w*4) = aw;
                *(uint2*)(sm + OF_MULH + (size_t)w*4) = mw;
            }
            const float4* pi4 = (const float4*)(Pa + ((size_t)b*NN + ii) * 64) + half*8;
            const float4* pj4 = (const float4*)(Pa + ((size_t)b*NN + jj) * 64) + half*8;
            #pragma unroll
            for (int q = 0; q < 8; q++) {
                float4 p = pi4[q], r = pj4[q];
                *(float4*)(sm + OF_PSUM + (size_t)(el*PSTR + half*32 + q*4)*4) =
                    make_float4(p.x+r.x, p.y+r.y, p.z+r.z, p.w+r.w);
            }
        }
        __syncthreads();

        /* ---- GEMM1: C1 = abs@Wb + mul@Wc (single fp16, fp32 acc) ---- */
        float acc[2][4][4];
        #pragma unroll
        for (int mt = 0; mt < 2; mt++)
            #pragma unroll
            for (int nt = 0; nt < 4; nt++)
                #pragma unroll
                for (int c = 0; c < 4; c++) acc[mt][nt][c] = 0.f;

        #pragma unroll
        for (int kc = 0; kc < 6; kc++) {
            uint32_t kb = kc * 32;
            uint32_t Aa[2][4], Am[2][4];
            ldsm4(Aa[0], aAbs + kb);
            ldsm4(Aa[1], aAbs + 16*208 + kb);
            ldsm4(Am[0], aMul + kb);
            ldsm4(Am[1], aMul + 16*208 + kb);
            uint32_t Bb[2][4], Bc[2][4];
            #pragma unroll
            for (int p = 0; p < 2; p++) {
                ldsm4(Bb[p], bWbh + p*16*208 + kb);
                ldsm4(Bc[p], bWch + p*16*208 + kb);
            }
            #pragma unroll
            for (int nt = 0; nt < 4; nt++) {
                int p = nt >> 1, q = (nt & 1) * 2;
                #pragma unroll
                for (int mt = 0; mt < 2; mt++) {
                    float* c = acc[mt][nt];
                    mma_f16(c, Aa[mt], Bb[p][q], Bb[p][q+1]);
                    mma_f16(c, Am[mt], Bc[p][q], Bc[p][q+1]);
                }
            }
        }

        /* ---- epilogue 1: z1 = prelu(C1 + psum + b1) -> fp16 ---- */
        {
            const float* sb1 = (const float*)(sm + OF_B1);
            #pragma unroll
            for (int mt = 0; mt < 2; mt++) {
                int r = mblk + mt*16 + g;
                #pragma unroll
                for (int nt = 0; nt < 4; nt++) {
                    int c = nhalf + nt*8 + 2*t;
                    float2 p0 = *(const float2*)(sm + OF_PSUM + (size_t)(r*PSTR + c)*4);
                    float2 p1 = *(const float2*)(sm + OF_PSUM + (size_t)((r+8)*PSTR + c)*4);
                    float bc0 = sb1[c], bc1 = sb1[c+1];
                    float u00 = acc[mt][nt][0] + p0.x + bc0; u00 = (u00 >= 0.f) ? u00 : a1*u00;
                    float u01 = acc[mt][nt][1] + p0.y + bc1; u01 = (u01 >= 0.f) ? u01 : a1*u01;
                    float u10 = acc[mt][nt][2] + p1.x + bc0; u10 = (u10 >= 0.f) ? u10 : a1*u10;
                    float u11 = acc[mt][nt][3] + p1.y + bc1; u11 = (u11 >= 0.f) ? u11 : a1*u11;
                    int w0 = r*ZKW + (c >> 1), w1 = (r+8)*ZKW + (c >> 1);
                    *(uint32_t*)(sm + OF_Z1H + (size_t)w0*4) = packh2(u00, u01);
                    *(uint32_t*)(sm + OF_Z1H + (size_t)w1*4) = packh2(u10, u11);
                }
            }
        }
        __syncthreads();

        /* ---- GEMM2: C2 = z1 @ W2 (single fp16) ---- */
        float acc2[2][4][4];
        #pragma unroll
        for (int mt = 0; mt < 2; mt++)
            #pragma unroll
            for (int nt = 0; nt < 4; nt++)
                #pragma unroll
                for (int c = 0; c < 4; c++) acc2[mt][nt][c] = 0.f;

        #pragma unroll
        for (int kc = 0; kc < 4; kc++) {
            uint32_t kb = kc * 32;
            uint32_t Zh[2][4];
            ldsm4(Zh[0], aZh + kb);
            ldsm4(Zh[1], aZh + 16*144 + kb);
            uint32_t B2[2][4];
            #pragma unroll
            for (int p = 0; p < 2; p++)
                ldsm4(B2[p], bW2h + p*16*144 + kb);
            #pragma unroll
            for (int nt = 0; nt < 4; nt++) {
                int p = nt >> 1, q = (nt & 1) * 2;
                #pragma unroll
                for (int mt = 0; mt < 2; mt++)
                    mma_f16(acc2[mt][nt], Zh[mt], B2[p][q], B2[p][q+1]);
            }
        }

        /* ---- epilogue 2: dot(prelu(C2 + b2), w3) -> red ---- */
        {
            const float* sb2 = (const float*)(sm + OF_B2);
            const float* sw3 = (const float*)(sm + OF_W3);
            float pr[2][2] = {{0.f,0.f},{0.f,0.f}};
            #pragma unroll
            for (int mt = 0; mt < 2; mt++) {
                #pragma unroll
                for (int nt = 0; nt < 4; nt++) {
                    int c = nhalf + nt*8 + 2*t;
                    float bc0 = sb2[c], bc1 = sb2[c+1];
                    float w0 = sw3[c],  w1 = sw3[c+1];
                    float u00 = acc2[mt][nt][0] + bc0; u00 = (u00 >= 0.f) ? u00 : a2*u00;
                    float u01 = acc2[mt][nt][1] + bc1; u01 = (u01 >= 0.f) ? u01 : a2*u01;
                    float u10 = acc2[mt][nt][2] + bc0; u10 = (u10 >= 0.f) ? u10 : a2*u10;
                    float u11 = acc2[mt][nt][3] + bc1; u11 = (u11 >= 0.f) ? u11 : a2*u11;
                    pr[mt][0] = fmaf(u00, w0, fmaf(u01, w1, pr[mt][0]));
                    pr[mt][1] = fmaf(u10, w0, fmaf(u11, w1, pr[mt][1]));
                }
            }
            #pragma unroll
            for (int mt = 0; mt < 2; mt++) {
                #pragma unroll
                for (int rr = 0; rr < 2; rr++) {
                    pr[mt][rr] += __shfl_xor_sync(0xffffffffu, pr[mt][rr], 1);
                    pr[mt][rr] += __shfl_xor_sync(0xffffffffu, pr[mt][rr], 2);
                }
            }
            if (t == 0) {
                float* red = (float*)(sm + OF_RED);
                int nh = wid >> 2;
                #pragma unroll
                for (int mt = 0; mt < 2; mt++) {
                    int r = mblk + mt*16 + g;
                    red[r*2 + nh]     = pr[mt][0];
                    red[(r+8)*2 + nh] = pr[mt][1];
                }
            }
        }
        __syncthreads();

        /* ---- out ---- */
        if (tid < ETD) {
            const float* red = (const float*)(sm + OF_RED);
            int eg = e0 + tid;
            if (eg < NEDGE)
                out[(size_t)b * NEDGE + eg] = red[tid*2] + red[tid*2 + 1] + b3;
        }
        /* next staging writes absh/mulh/psum (disjoint from red/z1);
           ordering vs these reads is enforced by the stage-end __syncthreads */
    }
}

/* ======================= host launcher ======================= */
extern "C" void kernel_launch(void* const* d_in, const int* in_sizes, int n_in,
                              void* d_out, int out_size) {
    (void)in_sizes; (void)n_in; (void)out_size;
    const float* nf    = (const float*)d_in[1];
    const float* sc    = (const float*)d_in[2];
    const float* smean = (const float*)d_in[3];
    const float* sstd  = (const float*)d_in[4];
    const float* We1   = (const float*)d_in[5];
    const float* be1   = (const float*)d_in[6];
    const float* ae1   = (const float*)d_in[7];
    const float* We2   = (const float*)d_in[8];
    const float* be2   = (const float*)d_in[9];
    const float* ae2   = (const float*)d_in[10];
    const float* Wd1   = (const float*)d_in[11];
    const float* bd1   = (const float*)d_in[12];
    const float* ad1   = (const float*)d_in[13];
    const float* Wd2   = (const float*)d_in[14];
    const float* bd2   = (const float*)d_in[15];
    const float* ad2   = (const float*)d_in[16];
    const float* Wd3   = (const float*)d_in[17];
    const float* bd3   = (const float*)d_in[18];
    const int*   ei    = (const int*)d_in[19];
    const int*   ej    = (const int*)d_in[20];
    float* out = (float*)d_out;

    float *pfeats, *ph1, *ph, *ppa;
    cudaGetSymbolAddress((void**)&pfeats, g_feats);
    cudaGetSymbolAddress((void**)&ph1,   g_h1);
    cudaGetSymbolAddress((void**)&ph,    g_h);
    cudaGetSymbolAddress((void**)&ppa,   g_Pa);

    cudaFuncSetAttribute(decoder_mma_kernel,
                         cudaFuncAttributeMaxDynamicSharedMemorySize, DEC_SMEM);

    reduce_mean_kernel<<<BATCH, 256>>>(sc);
    build_feats_kernel<<<(NROWS*FEATDIM + 255)/256, 256>>>(nf, sc, smean, sstd);
    gemm_kernel<<<dim3(NROWS/64, 2), 256>>>(pfeats, We1, be1, ae1, ph1, NROWS, FEATDIM, HIDDIM);
    gemm_kernel<<<dim3(NROWS/64, 2), 256>>>(ph1, We2, be2, ae2, ph, NROWS, HIDDIM, HIDDIM);
    gemm_kernel<<<dim3(NROWS/64, 1), 256>>>(ph, Wd1, nullptr, nullptr, ppa, NROWS, HIDDIM, DECDIM);
    decoder_mma_kernel<<<NCTA, 256, DEC_SMEM>>>(
        ph, ppa, Wd1, bd1, ad1, Wd2, bd2, ad2, Wd3, bd3, ei, ej, out);
}

// round 9
// speedup vs baseline: 4.5180x; 1.1800x over previous
#include <cuda_runtime.h>
#include <cuda_fp16.h>
#include <cstdint>

#define BATCH   16
#define NN      400
#define HIDDIM  96
#define DECDIM  64
#define NEDGE   79800
#define NROWS   (BATCH*NN)      /* 6400 */
#define FEATDIM 408
#define EPSF    1e-8f

#define ETD     128             /* edges per tile */
#define NTILE   624             /* ceil(79800/128) */
#define NWORK   (NTILE*BATCH)   /* 9984 */
#define NCTA_DEC 296            /* 2 CTAs per SM */

/* strides: k=96 arrays padded to 104 halves (208B row, conflict-free ldmatrix
   perm 20*g mod 32); k=64 arrays 72 halves (144B, perm 4*g). */
#define AKW   52
#define ZKW   36

/* ---- smem byte offsets (total 110336 B = 107.8 KB -> 2 CTAs/SM) ---- */
#define OF_ABSH 0               /* 128x104 f16 = 26624 */
#define OF_MULH 26624
#define OF_WBH  53248           /* 64x104 f16 = 13312 */
#define OF_WCH  66560
#define OF_W2H  79872           /* 64x72 f16 = 9216 */
#define OF_B1   89088
#define OF_B2   89344
#define OF_W3   89600
#define OF_Z1H  89856           /* 128x72 f16 = 18432 */
#define OF_RED  108288          /* 128x2 f32 = 1024 */
#define OF_EI   109312          /* 128 int */
#define OF_EJ   109824
#define DEC_SMEM 110336

/* -------- scratch (device globals; no runtime allocation allowed) -------- */
__device__ float g_inv[BATCH];
__device__ float g_feats[NROWS*FEATDIM];
__device__ float g_h1[NROWS*HIDDIM];
__device__ float g_h[NROWS*HIDDIM];
__device__ float g_Pa[NROWS*DECDIM];

/* ======================= helpers ======================= */
__device__ __forceinline__ uint32_t smem_u32(const void* p) {
    uint32_t a;
    asm("{ .reg .u64 t; cvta.to.shared.u64 t, %1; cvt.u32.u64 %0, t; }" : "=r"(a) : "l"(p));
    return a;
}
__device__ __forceinline__ uint32_t packh2(float x0, float x1) {
    __half2 hh = __floats2half2_rn(x0, x1);
    return *reinterpret_cast<uint32_t*>(&hh);
}
__device__ __forceinline__ void ldsm4(uint32_t* r, uint32_t a) {
    asm volatile("ldmatrix.sync.aligned.m8n8.x4.shared.b16 {%0,%1,%2,%3}, [%4];"
                 : "=r"(r[0]), "=r"(r[1]), "=r"(r[2]), "=r"(r[3]) : "r"(a));
}
__device__ __forceinline__ void mma_f16(float* c, const uint32_t* a, uint32_t b0, uint32_t b1) {
    asm volatile("mma.sync.aligned.m16n8k16.row.col.f32.f16.f16.f32 "
                 "{%0,%1,%2,%3}, {%4,%5,%6,%7}, {%8,%9}, {%0,%1,%2,%3};"
                 : "+f"(c[0]), "+f"(c[1]), "+f"(c[2]), "+f"(c[3])
                 : "r"(a[0]), "r"(a[1]), "r"(a[2]), "r"(a[3]), "r"(b0), "r"(b1));
}

/* ======================= encoder kernels ======================= */
__global__ void reduce_mean_kernel(const float* __restrict__ sc) {
    __shared__ float red[256];
    int b = blockIdx.x;
    const float* p = sc + (size_t)b * NN * NN;
    float s = 0.f;
    for (int i = threadIdx.x; i < NN*NN; i += 256) s += p[i];
    red[threadIdx.x] = s;
    __syncthreads();
    for (int st = 128; st > 0; st >>= 1) {
        if (threadIdx.x < st) red[threadIdx.x] += red[threadIdx.x + st];
        __syncthreads();
    }
    if (threadIdx.x == 0) g_inv[b] = 1.f / fmaxf(red[0] * (1.f/(float)(NN*NN)), EPSF);
}

__global__ void build_feats_kernel(const float* __restrict__ nf, const float* __restrict__ sc,
                                   const float* __restrict__ smean, const float* __restrict__ sstd) {
    int idx = blockIdx.x * blockDim.x + threadIdx.x;
    if (idx >= NROWS*FEATDIM) return;
    int r = idx / FEATDIM;
    int c = idx - r * FEATDIM;
    float v;
    if (c < 8) v = (nf[r*8 + c] - smean[c]) / (sstd[c] + EPSF);
    else       v = sc[(size_t)r*NN + (c-8)] * g_inv[r / NN];
    g_feats[idx] = v;
}

__global__ __launch_bounds__(256) void gemm_kernel(
    const float* __restrict__ A, const float* __restrict__ W,
    const float* __restrict__ bias, const float* __restrict__ alphap,
    float* __restrict__ C, int M, int K, int N)
{
    __shared__ float As[8][64];
    __shared__ float Bs[8][64];
    int tid = threadIdx.x;
    int m0 = blockIdx.x * 64, n0 = blockIdx.y * 64;
    int ty = tid >> 4, tx = tid & 15;
    float acc[4][4] = {};
    for (int k0 = 0; k0 < K; k0 += 8) {
        #pragma unroll
        for (int i = tid; i < 512; i += 256) {
            int m = i >> 3, k = i & 7;
            As[k][m] = A[(size_t)(m0 + m) * K + (k0 + k)];
        }
        #pragma unroll
        for (int i = tid; i < 512; i += 256) {
            int k = i >> 6, n = i & 63;
            Bs[k][n] = (n0 + n < N) ? W[(size_t)(k0 + k) * N + (n0 + n)] : 0.f;
        }
        __syncthreads();
        #pragma unroll
        for (int kk = 0; kk < 8; kk++) {
            float4 a  = *(const float4*)&As[kk][ty*4];
            float4 bv = *(const float4*)&Bs[kk][tx*4];
            float av[4] = {a.x, a.y, a.z, a.w};
            float bw[4] = {bv.x, bv.y, bv.z, bv.w};
            #pragma unroll
            for (int i2 = 0; i2 < 4; i2++)
                #pragma unroll
                for (int j2 = 0; j2 < 4; j2++)
                    acc[i2][j2] = fmaf(av[i2], bw[j2], acc[i2][j2]);
        }
        __syncthreads();
    }
    float alpha = alphap ? alphap[0] : 0.f;
    bool act = (alphap != nullptr);
    #pragma unroll
    for (int i2 = 0; i2 < 4; i2++) {
        int row = m0 + ty*4 + i2;
        #pragma unroll
        for (int j2 = 0; j2 < 4; j2++) {
            int col = n0 + tx*4 + j2;
            if (col < N) {
                float v = acc[i2][j2] + (bias ? bias[col] : 0.f);
                if (act) v = (v >= 0.f) ? v : alpha * v;
                C[(size_t)row * N + col] = v;
            }
        }
    }
}

/* ======================= fp16 mma.sync persistent decoder (occ=2) ======================= */
__global__ __launch_bounds__(256, 2)
void decoder_mma_kernel(
    const float* __restrict__ h, const float* __restrict__ Pa,
    const float* __restrict__ Wd1, const float* __restrict__ b1,
    const float* __restrict__ a1p, const float* __restrict__ W2,
    const float* __restrict__ b2, const float* __restrict__ a2p,
    const float* __restrict__ W3, const float* __restrict__ b3p,
    const int* __restrict__ ei, const int* __restrict__ ej,
    float* __restrict__ out)
{
    extern __shared__ char sm[];
    uint32_t smb = smem_u32(sm);
    int tid  = threadIdx.x;
    int wid  = tid >> 5;
    int lane = tid & 31;
    int g    = lane >> 2;
    int t    = lane & 3;
    int mblk  = (wid & 3) * 32;
    int nhalf = (wid >> 2) * 32;

    /* ---- stage weights once (single fp16, [n][k]) ---- */
    for (int idx = tid; idx < 64*96; idx += 256) {
        int n = idx / 96, k = idx - n * 96;
        int o = n * 104 + k;
        ((__half*)(sm + OF_WBH))[o] = __float2half_rn(Wd1[(96  + k)*64 + n]);
        ((__half*)(sm + OF_WCH))[o] = __float2half_rn(Wd1[(192 + k)*64 + n]);
    }
    for (int idx = tid; idx < 64*64; idx += 256) {
        int n = idx >> 6, k = idx & 63;
        ((__half*)(sm + OF_W2H))[n * 72 + k] = __float2half_rn(W2[k*64 + n]);
    }
    if (tid < 64) {
        ((float*)(sm + OF_B1))[tid] = b1[tid];
        ((float*)(sm + OF_B2))[tid] = b2[tid];
        ((float*)(sm + OF_W3))[tid] = W3[tid];
    }
    float a1 = a1p[0], a2 = a2p[0], b3 = b3p[0];
    __syncthreads();

    /* per-warp ldmatrix lane address components */
    uint32_t laneA  = (uint32_t)((lane & 15)*208 + (lane >> 4)*16);
    uint32_t laneB  = (uint32_t)(((lane >> 4)*8 + (lane & 7))*208 + ((lane >> 3) & 1)*16);
    uint32_t laneAz = (uint32_t)((lane & 15)*144 + (lane >> 4)*16);
    uint32_t laneBz = (uint32_t)(((lane >> 4)*8 + (lane & 7))*144 + ((lane >> 3) & 1)*16);

    uint32_t aAbs = smb + OF_ABSH + mblk*208 + laneA;
    uint32_t aMul = smb + OF_MULH + mblk*208 + laneA;
    uint32_t bWbh = smb + OF_WBH + nhalf*208 + laneB;
    uint32_t bWch = smb + OF_WCH + nhalf*208 + laneB;
    uint32_t aZh  = smb + OF_Z1H + mblk*144 + laneAz;
    uint32_t bW2h = smb + OF_W2H + nhalf*144 + laneBz;

    const int* s_ei = (const int*)(sm + OF_EI);
    const int* s_ej = (const int*)(sm + OF_EJ);

    for (int work = blockIdx.x; work < NWORK; work += NCTA_DEC) {
        int b  = work / NTILE;
        int tt = work - b * NTILE;
        int e0 = tt * ETD;

        /* ---- stage: edge indices + abs/mul fp16 ---- */
        if (tid < ETD) {
            int e = e0 + tid; if (e >= NEDGE) e = NEDGE - 1;
            ((int*)(sm + OF_EI))[tid] = ei[e];
            ((int*)(sm + OF_EJ))[tid] = ej[e];
        }
        {
            int el = tid >> 1, half = tid & 1;
            int e = e0 + el; if (e >= NEDGE) e = NEDGE - 1;
            int ii = ei[e], jj = ej[e];
            const float4* hi4 = (const float4*)(h + ((size_t)b*NN + ii) * 96) + half*12;
            const float4* hj4 = (const float4*)(h + ((size_t)b*NN + jj) * 96) + half*12;
            #pragma unroll
            for (int q = 0; q < 12; q++) {
                float4 x = hi4[q], y = hj4[q];
                uint2 aw = make_uint2(packh2(fabsf(x.x - y.x), fabsf(x.y - y.y)),
                                      packh2(fabsf(x.z - y.z), fabsf(x.w - y.w)));
                uint2 mw = make_uint2(packh2(x.x*y.x, x.y*y.y), packh2(x.z*y.z, x.w*y.w));
                int w = el*AKW + half*24 + q*2;
                *(uint2*)(sm + OF_ABSH + (size_t)w*4) = aw;
                *(uint2*)(sm + OF_MULH + (size_t)w*4) = mw;
            }
        }
        __syncthreads();

        /* ---- GEMM1: C1 = abs@Wb + mul@Wc (single fp16, fp32 acc) ---- */
        float acc[2][4][4];
        #pragma unroll
        for (int mt = 0; mt < 2; mt++)
            #pragma unroll
            for (int nt = 0; nt < 4; nt++)
                #pragma unroll
                for (int c = 0; c < 4; c++) acc[mt][nt][c] = 0.f;

        #pragma unroll
        for (int kc = 0; kc < 6; kc++) {
            uint32_t kb = kc * 32;
            uint32_t Aa[2][4], Am[2][4];
            ldsm4(Aa[0], aAbs + kb);
            ldsm4(Aa[1], aAbs + 16*208 + kb);
            ldsm4(Am[0], aMul + kb);
            ldsm4(Am[1], aMul + 16*208 + kb);
            uint32_t Bb[2][4], Bc[2][4];
            #pragma unroll
            for (int p = 0; p < 2; p++) {
                ldsm4(Bb[p], bWbh + p*16*208 + kb);
                ldsm4(Bc[p], bWch + p*16*208 + kb);
            }
            #pragma unroll
            for (int nt = 0; nt < 4; nt++) {
                int p = nt >> 1, q = (nt & 1) * 2;
                #pragma unroll
                for (int mt = 0; mt < 2; mt++) {
                    float* c = acc[mt][nt];
                    mma_f16(c, Aa[mt], Bb[p][q], Bb[p][q+1]);
                    mma_f16(c, Am[mt], Bc[p][q], Bc[p][q+1]);
                }
            }
        }

        /* ---- epilogue 1: z1 = prelu(C1 + (Pa_i+Pa_j) + b1) -> fp16
               Pa gathered directly from global (L2-resident) ---- */
        {
            const float* sb1 = (const float*)(sm + OF_B1);
            #pragma unroll
            for (int mt = 0; mt < 2; mt++) {
                int r = mblk + mt*16 + g;
                const float* pi0 = Pa + ((size_t)b*NN + s_ei[r]) * 64;
                const float* pj0 = Pa + ((size_t)b*NN + s_ej[r]) * 64;
                const float* pi1 = Pa + ((size_t)b*NN + s_ei[r+8]) * 64;
                const float* pj1 = Pa + ((size_t)b*NN + s_ej[r+8]) * 64;
                #pragma unroll
                for (int nt = 0; nt < 4; nt++) {
                    int c = nhalf + nt*8 + 2*t;
                    float2 A0 = *(const float2*)(pi0 + c);
                    float2 B0 = *(const float2*)(pj0 + c);
                    float2 A1 = *(const float2*)(pi1 + c);
                    float2 B1 = *(const float2*)(pj1 + c);
                    float bc0 = sb1[c], bc1 = sb1[c+1];
                    float u00 = acc[mt][nt][0] + A0.x + B0.x + bc0; u00 = (u00 >= 0.f) ? u00 : a1*u00;
                    float u01 = acc[mt][nt][1] + A0.y + B0.y + bc1; u01 = (u01 >= 0.f) ? u01 : a1*u01;
                    float u10 = acc[mt][nt][2] + A1.x + B1.x + bc0; u10 = (u10 >= 0.f) ? u10 : a1*u10;
                    float u11 = acc[mt][nt][3] + A1.y + B1.y + bc1; u11 = (u11 >= 0.f) ? u11 : a1*u11;
                    int w0 = r*ZKW + (c >> 1), w1 = (r+8)*ZKW + (c >> 1);
                    *(uint32_t*)(sm + OF_Z1H + (size_t)w0*4) = packh2(u00, u01);
                    *(uint32_t*)(sm + OF_Z1H + (size_t)w1*4) = packh2(u10, u11);
                }
            }
        }
        __syncthreads();

        /* ---- GEMM2: C2 = z1 @ W2 (single fp16) ---- */
        float acc2[2][4][4];
        #pragma unroll
        for (int mt = 0; mt < 2; mt++)
            #pragma unroll
            for (int nt = 0; nt < 4; nt++)
                #pragma unroll
                for (int c = 0; c < 4; c++) acc2[mt][nt][c] = 0.f;

        #pragma unroll
        for (int kc = 0; kc < 4; kc++) {
            uint32_t kb = kc * 32;
            uint32_t Zh[2][4];
            ldsm4(Zh[0], aZh + kb);
            ldsm4(Zh[1], aZh + 16*144 + kb);
            uint32_t B2[2][4];
            #pragma unroll
            for (int p = 0; p < 2; p++)
                ldsm4(B2[p], bW2h + p*16*144 + kb);
            #pragma unroll
            for (int nt = 0; nt < 4; nt++) {
                int p = nt >> 1, q = (nt & 1) * 2;
                #pragma unroll
                for (int mt = 0; mt < 2; mt++)
                    mma_f16(acc2[mt][nt], Zh[mt], B2[p][q], B2[p][q+1]);
            }
        }

        /* ---- epilogue 2: dot(prelu(C2 + b2), w3) -> red ---- */
        {
            const float* sb2 = (const float*)(sm + OF_B2);
            const float* sw3 = (const float*)(sm + OF_W3);
            float pr[2][2] = {{0.f,0.f},{0.f,0.f}};
            #pragma unroll
            for (int mt = 0; mt < 2; mt++) {
                #pragma unroll
                for (int nt = 0; nt < 4; nt++) {
                    int c = nhalf + nt*8 + 2*t;
                    float bc0 = sb2[c], bc1 = sb2[c+1];
                    float w0 = sw3[c],  w1 = sw3[c+1];
                    float u00 = acc2[mt][nt][0] + bc0; u00 = (u00 >= 0.f) ? u00 : a2*u00;
                    float u01 = acc2[mt][nt][1] + bc1; u01 = (u01 >= 0.f) ? u01 : a2*u01;
                    float u10 = acc2[mt][nt][2] + bc0; u10 = (u10 >= 0.f) ? u10 : a2*u10;
                    float u11 = acc2[mt][nt][3] + bc1; u11 = (u11 >= 0.f) ? u11 : a2*u11;
                    pr[mt][0] = fmaf(u00, w0, fmaf(u01, w1, pr[mt][0]));
                    pr[mt][1] = fmaf(u10, w0, fmaf(u11, w1, pr[mt][1]));
                }
            }
            #pragma unroll
            for (int mt = 0; mt < 2; mt++) {
                #pragma unroll
                for (int rr = 0; rr < 2; rr++) {
                    pr[mt][rr] += __shfl_xor_sync(0xffffffffu, pr[mt][rr], 1);
                    pr[mt][rr] += __shfl_xor_sync(0xffffffffu, pr[mt][rr], 2);
                }
            }
            if (t == 0) {
                float* red = (float*)(sm + OF_RED);
                int nh = wid >> 2;
                #pragma unroll
                for (int mt = 0; mt < 2; mt++) {
                    int r = mblk + mt*16 + g;
                    red[r*2 + nh]     = pr[mt][0];
                    red[(r+8)*2 + nh] = pr[mt][1];
                }
            }
        }
        __syncthreads();

        /* ---- out ---- */
        if (tid < ETD) {
            const float* red = (const float*)(sm + OF_RED);
            int eg = e0 + tid;
            if (eg < NEDGE)
                out[(size_t)b * NEDGE + eg] = red[tid*2] + red[tid*2 + 1] + b3;
        }
        /* next staging writes absh/mulh/ei/ej (disjoint from red);
           ordering vs red reads is enforced by the stage-end __syncthreads */
    }
}

/* ======================= host launcher ======================= */
extern "C" void kernel_launch(void* const* d_in, const int* in_sizes, int n_in,
                              void* d_out, int out_size) {
    (void)in_sizes; (void)n_in; (void)out_size;
    const float* nf    = (const float*)d_in[1];
    const float* sc    = (const float*)d_in[2];
    const float* smean = (const float*)d_in[3];
    const float* sstd  = (const float*)d_in[4];
    const float* We1   = (const float*)d_in[5];
    const float* be1   = (const float*)d_in[6];
    const float* ae1   = (const float*)d_in[7];
    const float* We2   = (const float*)d_in[8];
    const float* be2   = (const float*)d_in[9];
    const float* ae2   = (const float*)d_in[10];
    const float* Wd1   = (const float*)d_in[11];
    const float* bd1   = (const float*)d_in[12];
    const float* ad1   = (const float*)d_in[13];
    const float* Wd2   = (const float*)d_in[14];
    const float* bd2   = (const float*)d_in[15];
    const float* ad2   = (const float*)d_in[16];
    const float* Wd3   = (const float*)d_in[17];
    const float* bd3   = (const float*)d_in[18];
    const int*   ei    = (const int*)d_in[19];
    const int*   ej    = (const int*)d_in[20];
    float* out = (float*)d_out;

    float *pfeats, *ph1, *ph, *ppa;
    cudaGetSymbolAddress((void**)&pfeats, g_feats);
    cudaGetSymbolAddress((void**)&ph1,   g_h1);
    cudaGetSymbolAddress((void**)&ph,    g_h);
    cudaGetSymbolAddress((void**)&ppa,   g_Pa);

    cudaFuncSetAttribute(decoder_mma_kernel,
                         cudaFuncAttributeMaxDynamicSharedMemorySize, DEC_SMEM);

    reduce_mean_kernel<<<BATCH, 256>>>(sc);
    build_feats_kernel<<<(NROWS*FEATDIM + 255)/256, 256>>>(nf, sc, smean, sstd);
    gemm_kernel<<<dim3(NROWS/64, 2), 256>>>(pfeats, We1, be1, ae1, ph1, NROWS, FEATDIM, HIDDIM);
    gemm_kernel<<<dim3(NROWS/64, 2), 256>>>(ph1, We2, be2, ae2, ph, NROWS, HIDDIM, HIDDIM);
    gemm_kernel<<<dim3(NROWS/64, 1), 256>>>(ph, Wd1, nullptr, nullptr, ppa, NROWS, HIDDIM, DECDIM);
    decoder_mma_kernel<<<NCTA_DEC, 256, DEC_SMEM>>>(
        ph, ppa, Wd1, bd1, ad1, Wd2, bd2, ad2, Wd3, bd3, ei, ej, out);
}

// round 10
// speedup vs baseline: 4.5557x; 1.0083x over previous
#include <cuda_runtime.h>
#include <cuda_fp16.h>
#include <cstdint>

#define BATCH   16
#define NN      400
#define HIDDIM  96
#define DECDIM  64
#define NEDGE   79800
#define NROWS   (BATCH*NN)      /* 6400 */
#define FEATDIM 408
#define EPSF    1e-8f

#define ETD     128             /* edges per tile */
#define NTILE   624             /* ceil(79800/128) */
#define NWORK   (NTILE*BATCH)   /* 9984 */
#define NCTA_DEC 296            /* 2 CTAs per SM */

/* strides: k=96 A arrays padded to 104 halves (208B rows, conflict-free ldmatrix
   perm 20*g mod 32); k=64 z array 72 halves (144B, perm 4*g). */
#define AKW   52
#define ZKW   36

/* ---- smem byte offsets (total 109312 B = 106.8 KB -> 2 CTAs/SM) ---- */
#define OF_ABSH 0               /* 128x104 f16 = 26624 */
#define OF_MULH 26624
#define OF_WBH  53248           /* 64x104 f16 = 13312 */
#define OF_WCH  66560
#define OF_W2H  79872           /* 64x72 f16 = 9216 */
#define OF_B1   89088
#define OF_B2   89344
#define OF_W3   89600
#define OF_PSZ  89856           /* psum then z1: 128x72 f16 = 18432 */
#define OF_RED  108288          /* 128x2 f32 = 1024 */
#define DEC_SMEM 109312

/* -------- scratch (device globals; no runtime allocation allowed) -------- */
__device__ float g_inv[BATCH];
__device__ float g_feats[NROWS*FEATDIM];
__device__ float g_h1[NROWS*HIDDIM];
__device__ float g_h[NROWS*HIDDIM];
__device__ float g_Pa[NROWS*DECDIM];

/* ======================= helpers ======================= */
__device__ __forceinline__ uint32_t smem_u32(const void* p) {
    uint32_t a;
    asm("{ .reg .u64 t; cvta.to.shared.u64 t, %1; cvt.u32.u64 %0, t; }" : "=r"(a) : "l"(p));
    return a;
}
__device__ __forceinline__ uint32_t packh2(float x0, float x1) {
    __half2 hh = __floats2half2_rn(x0, x1);
    return *reinterpret_cast<uint32_t*>(&hh);
}
__device__ __forceinline__ float2 unpackh2(uint32_t w) {
    __half2 hh = *reinterpret_cast<__half2*>(&w);
    return __half22float2(hh);
}
__device__ __forceinline__ void ldsm4(uint32_t* r, uint32_t a) {
    asm volatile("ldmatrix.sync.aligned.m8n8.x4.shared.b16 {%0,%1,%2,%3}, [%4];"
                 : "=r"(r[0]), "=r"(r[1]), "=r"(r[2]), "=r"(r[3]) : "r"(a));
}
__device__ __forceinline__ void mma_f16(float* c, const uint32_t* a, uint32_t b0, uint32_t b1) {
    asm volatile("mma.sync.aligned.m16n8k16.row.col.f32.f16.f16.f32 "
                 "{%0,%1,%2,%3}, {%4,%5,%6,%7}, {%8,%9}, {%0,%1,%2,%3};"
                 : "+f"(c[0]), "+f"(c[1]), "+f"(c[2]), "+f"(c[3])
                 : "r"(a[0]), "r"(a[1]), "r"(a[2]), "r"(a[3]), "r"(b0), "r"(b1));
}

/* ======================= encoder kernels ======================= */
__global__ void reduce_mean_kernel(const float* __restrict__ sc) {
    __shared__ float red[256];
    int b = blockIdx.x;
    const float* p = sc + (size_t)b * NN * NN;
    float s = 0.f;
    for (int i = threadIdx.x; i < NN*NN; i += 256) s += p[i];
    red[threadIdx.x] = s;
    __syncthreads();
    for (int st = 128; st > 0; st >>= 1) {
        if (threadIdx.x < st) red[threadIdx.x] += red[threadIdx.x + st];
        __syncthreads();
    }
    if (threadIdx.x == 0) g_inv[b] = 1.f / fmaxf(red[0] * (1.f/(float)(NN*NN)), EPSF);
}

__global__ void build_feats_kernel(const float* __restrict__ nf, const float* __restrict__ sc,
                                   const float* __restrict__ smean, const float* __restrict__ sstd) {
    int idx = blockIdx.x * blockDim.x + threadIdx.x;
    if (idx >= NROWS*FEATDIM) return;
    int r = idx / FEATDIM;
    int c = idx - r * FEATDIM;
    float v;
    if (c < 8) v = (nf[r*8 + c] - smean[c]) / (sstd[c] + EPSF);
    else       v = sc[(size_t)r*NN + (c-8)] * g_inv[r / NN];
    g_feats[idx] = v;
}

__global__ __launch_bounds__(256) void gemm_kernel(
    const float* __restrict__ A, const float* __restrict__ W,
    const float* __restrict__ bias, const float* __restrict__ alphap,
    float* __restrict__ C, int M, int K, int N)
{
    __shared__ float As[8][64];
    __shared__ float Bs[8][64];
    int tid = threadIdx.x;
    int m0 = blockIdx.x * 64, n0 = blockIdx.y * 64;
    int ty = tid >> 4, tx = tid & 15;
    float acc[4][4] = {};
    for (int k0 = 0; k0 < K; k0 += 8) {
        #pragma unroll
        for (int i = tid; i < 512; i += 256) {
            int m = i >> 3, k = i & 7;
            As[k][m] = A[(size_t)(m0 + m) * K + (k0 + k)];
        }
        #pragma unroll
        for (int i = tid; i < 512; i += 256) {
            int k = i >> 6, n = i & 63;
            Bs[k][n] = (n0 + n < N) ? W[(size_t)(k0 + k) * N + (n0 + n)] : 0.f;
        }
        __syncthreads();
        #pragma unroll
        for (int kk = 0; kk < 8; kk++) {
            float4 a  = *(const float4*)&As[kk][ty*4];
            float4 bv = *(const float4*)&Bs[kk][tx*4];
            float av[4] = {a.x, a.y, a.z, a.w};
            float bw[4] = {bv.x, bv.y, bv.z, bv.w};
            #pragma unroll
            for (int i2 = 0; i2 < 4; i2++)
                #pragma unroll
                for (int j2 = 0; j2 < 4; j2++)
                    acc[i2][j2] = fmaf(av[i2], bw[j2], acc[i2][j2]);
        }
        __syncthreads();
    }
    float alpha = alphap ? alphap[0] : 0.f;
    bool act = (alphap != nullptr);
    #pragma unroll
    for (int i2 = 0; i2 < 4; i2++) {
        int row = m0 + ty*4 + i2;
        #pragma unroll
        for (int j2 = 0; j2 < 4; j2++) {
            int col = n0 + tx*4 + j2;
            if (col < N) {
                float v = acc[i2][j2] + (bias ? bias[col] : 0.f);
                if (act) v = (v >= 0.f) ? v : alpha * v;
                C[(size_t)row * N + col] = v;
            }
        }
    }
}

/* ======================= fp16 mma.sync persistent decoder (occ=2, coop gather) ======================= */
__global__ __launch_bounds__(256, 2)
void decoder_mma_kernel(
    const float* __restrict__ h, const float* __restrict__ Pa,
    const float* __restrict__ Wd1, const float* __restrict__ b1,
    const float* __restrict__ a1p, const float* __restrict__ W2,
    const float* __restrict__ b2, const float* __restrict__ a2p,
    const float* __restrict__ W3, const float* __restrict__ b3p,
    const int* __restrict__ ei, const int* __restrict__ ej,
    float* __restrict__ out)
{
    extern __shared__ char sm[];
    uint32_t smb = smem_u32(sm);
    int tid  = threadIdx.x;
    int wid  = tid >> 5;
    int lane = tid & 31;
    int g    = lane >> 2;
    int t    = lane & 3;
    int mblk  = (wid & 3) * 32;
    int nhalf = (wid >> 2) * 32;

    /* ---- stage weights once (single fp16, [n][k]) ---- */
    for (int idx = tid; idx < 64*96; idx += 256) {
        int n = idx / 96, k = idx - n * 96;
        int o = n * 104 + k;
        ((__half*)(sm + OF_WBH))[o] = __float2half_rn(Wd1[(96  + k)*64 + n]);
        ((__half*)(sm + OF_WCH))[o] = __float2half_rn(Wd1[(192 + k)*64 + n]);
    }
    for (int idx = tid; idx < 64*64; idx += 256) {
        int n = idx >> 6, k = idx & 63;
        ((__half*)(sm + OF_W2H))[n * 72 + k] = __float2half_rn(W2[k*64 + n]);
    }
    if (tid < 64) {
        ((float*)(sm + OF_B1))[tid] = b1[tid];
        ((float*)(sm + OF_B2))[tid] = b2[tid];
        ((float*)(sm + OF_W3))[tid] = W3[tid];
    }
    float a1 = a1p[0], a2 = a2p[0], b3 = b3p[0];
    __syncthreads();

    /* per-warp ldmatrix lane address components */
    uint32_t laneA  = (uint32_t)((lane & 15)*208 + (lane >> 4)*16);
    uint32_t laneB  = (uint32_t)(((lane >> 4)*8 + (lane & 7))*208 + ((lane >> 3) & 1)*16);
    uint32_t laneAz = (uint32_t)((lane & 15)*144 + (lane >> 4)*16);
    uint32_t laneBz = (uint32_t)(((lane >> 4)*8 + (lane & 7))*144 + ((lane >> 3) & 1)*16);

    uint32_t aAbs = smb + OF_ABSH + mblk*208 + laneA;
    uint32_t aMul = smb + OF_MULH + mblk*208 + laneA;
    uint32_t bWbh = smb + OF_WBH + nhalf*208 + laneB;
    uint32_t bWch = smb + OF_WCH + nhalf*208 + laneB;
    uint32_t aZh  = smb + OF_PSZ + mblk*144 + laneAz;
    uint32_t bW2h = smb + OF_W2H + nhalf*144 + laneBz;

    for (int work = blockIdx.x; work < NWORK; work += NCTA_DEC) {
        int b  = work / NTILE;
        int tt = work - b * NTILE;
        int e0 = tt * ETD;

        /* ---- stage (warp-cooperative): each warp owns 16 edges ---- */
        {
            int ew = e0 + (wid << 4);
            /* indices in registers: lanes 0-15 -> ei, lanes 16-31 -> ej */
            int myidx;
            {
                int e = ew + (lane & 15); if (e >= NEDGE) e = NEDGE - 1;
                myidx = (lane < 16) ? ei[e] : ej[e];
            }

            /* h gather: per edge, lanes 0-23 cover the full 384B row (24 x 16B) */
            #pragma unroll 4
            for (int e = 0; e < 16; e++) {
                int ii = __shfl_sync(0xffffffffu, myidx, e);
                int jj = __shfl_sync(0xffffffffu, myidx, e + 16);
                if (lane < 24) {
                    const float4* hi4 = (const float4*)(h + ((size_t)b*NN + ii) * 96);
                    const float4* hj4 = (const float4*)(h + ((size_t)b*NN + jj) * 96);
                    float4 x = hi4[lane];
                    float4 y = hj4[lane];
                    uint2 aw = make_uint2(packh2(fabsf(x.x - y.x), fabsf(x.y - y.y)),
                                          packh2(fabsf(x.z - y.z), fabsf(x.w - y.w)));
                    uint2 mw = make_uint2(packh2(x.x*y.x, x.y*y.y), packh2(x.z*y.z, x.w*y.w));
                    int row = (wid << 4) + e;
                    *(uint2*)(sm + OF_ABSH + (size_t)row*208 + lane*8) = aw;
                    *(uint2*)(sm + OF_MULH + (size_t)row*208 + lane*8) = mw;
                }
            }

            /* Pa gather: per edge, lanes 0-15 load Pa_i row, 16-31 load Pa_j row */
            #pragma unroll 4
            for (int e = 0; e < 16; e++) {
                int nidx = __shfl_sync(0xffffffffu, myidx, e + (lane & 16));
                int l = lane & 15;
                const float4* pr = (const float4*)(Pa + ((size_t)b*NN + nidx) * 64);
                float4 u = pr[l];
                float4 v;
                v.x = __shfl_down_sync(0xffffffffu, u.x, 16);
                v.y = __shfl_down_sync(0xffffffffu, u.y, 16);
                v.z = __shfl_down_sync(0xffffffffu, u.z, 16);
                v.w = __shfl_down_sync(0xffffffffu, u.w, 16);
                if (lane < 16) {
                    uint2 w = make_uint2(packh2(u.x + v.x, u.y + v.y),
                                         packh2(u.z + v.z, u.w + v.w));
                    int row = (wid << 4) + e;
                    *(uint2*)(sm + OF_PSZ + (size_t)row*144 + l*8) = w;
                }
            }
        }
        __syncthreads();

        /* ---- GEMM1: C1 = abs@Wb + mul@Wc (single fp16, fp32 acc) ---- */
        float acc[2][4][4];
        #pragma unroll
        for (int mt = 0; mt < 2; mt++)
            #pragma unroll
            for (int nt = 0; nt < 4; nt++)
                #pragma unroll
                for (int c = 0; c < 4; c++) acc[mt][nt][c] = 0.f;

        #pragma unroll
        for (int kc = 0; kc < 6; kc++) {
            uint32_t kb = kc * 32;
            uint32_t Aa[2][4], Am[2][4];
            ldsm4(Aa[0], aAbs + kb);
            ldsm4(Aa[1], aAbs + 16*208 + kb);
            ldsm4(Am[0], aMul + kb);
            ldsm4(Am[1], aMul + 16*208 + kb);
            uint32_t Bb[2][4], Bc[2][4];
            #pragma unroll
            for (int p = 0; p < 2; p++) {
                ldsm4(Bb[p], bWbh + p*16*208 + kb);
                ldsm4(Bc[p], bWch + p*16*208 + kb);
            }
            #pragma unroll
            for (int nt = 0; nt < 4; nt++) {
                int p = nt >> 1, q = (nt & 1) * 2;
                #pragma unroll
                for (int mt = 0; mt < 2; mt++) {
                    float* c = acc[mt][nt];
                    mma_f16(c, Aa[mt], Bb[p][q], Bb[p][q+1]);
                    mma_f16(c, Am[mt], Bc[p][q], Bc[p][q+1]);
                }
            }
        }

        /* ---- epilogue 1: z1 = prelu(C1 + psum + b1); psum slots overwritten in place ---- */
        {
            const float* sb1 = (const float*)(sm + OF_B1);
            #pragma unroll
            for (int mt = 0; mt < 2; mt++) {
                int r = mblk + mt*16 + g;
                #pragma unroll
                for (int nt = 0; nt < 4; nt++) {
                    int c = nhalf + nt*8 + 2*t;
                    uint32_t pw0 = *(uint32_t*)(sm + OF_PSZ + (size_t)r*144 + c*2);
                    uint32_t pw1 = *(uint32_t*)(sm + OF_PSZ + (size_t)(r+8)*144 + c*2);
                    float2 p0 = unpackh2(pw0);
                    float2 p1 = unpackh2(pw1);
                    float bc0 = sb1[c], bc1 = sb1[c+1];
                    float u00 = acc[mt][nt][0] + p0.x + bc0; u00 = (u00 >= 0.f) ? u00 : a1*u00;
                    float u01 = acc[mt][nt][1] + p0.y + bc1; u01 = (u01 >= 0.f) ? u01 : a1*u01;
                    float u10 = acc[mt][nt][2] + p1.x + bc0; u10 = (u10 >= 0.f) ? u10 : a1*u10;
                    float u11 = acc[mt][nt][3] + p1.y + bc1; u11 = (u11 >= 0.f) ? u11 : a1*u11;
                    *(uint32_t*)(sm + OF_PSZ + (size_t)r*144 + c*2)     = packh2(u00, u01);
                    *(uint32_t*)(sm + OF_PSZ + (size_t)(r+8)*144 + c*2) = packh2(u10, u11);
                }
            }
        }
        __syncthreads();

        /* ---- GEMM2: C2 = z1 @ W2 (single fp16) ---- */
        float acc2[2][4][4];
        #pragma unroll
        for (int mt = 0; mt < 2; mt++)
            #pragma unroll
            for (int nt = 0; nt < 4; nt++)
                #pragma unroll
                for (int c = 0; c < 4; c++) acc2[mt][nt][c] = 0.f;

        #pragma unroll
        for (int kc = 0; kc < 4; kc++) {
            uint32_t kb = kc * 32;
            uint32_t Zh[2][4];
            ldsm4(Zh[0], aZh + kb);
            ldsm4(Zh[1], aZh + 16*144 + kb);
            uint32_t B2[2][4];
            #pragma unroll
            for (int p = 0; p < 2; p++)
                ldsm4(B2[p], bW2h + p*16*144 + kb);
            #pragma unroll
            for (int nt = 0; nt < 4; nt++) {
                int p = nt >> 1, q = (nt & 1) * 2;
                #pragma unroll
                for (int mt = 0; mt < 2; mt++)
                    mma_f16(acc2[mt][nt], Zh[mt], B2[p][q], B2[p][q+1]);
            }
        }

        /* ---- epilogue 2: dot(prelu(C2 + b2), w3) -> red ---- */
        {
            const float* sb2 = (const float*)(sm + OF_B2);
            const float* sw3 = (const float*)(sm + OF_W3);
            float pr[2][2] = {{0.f,0.f},{0.f,0.f}};
            #pragma unroll
            for (int mt = 0; mt < 2; mt++) {
                #pragma unroll
                for (int nt = 0; nt < 4; nt++) {
                    int c = nhalf + nt*8 + 2*t;
                    float bc0 = sb2[c], bc1 = sb2[c+1];
                    float w0 = sw3[c],  w1 = sw3[c+1];
                    float u00 = acc2[mt][nt][0] + bc0; u00 = (u00 >= 0.f) ? u00 : a2*u00;
                    float u01 = acc2[mt][nt][1] + bc1; u01 = (u01 >= 0.f) ? u01 : a2*u01;
                    float u10 = acc2[mt][nt][2] + bc0; u10 = (u10 >= 0.f) ? u10 : a2*u10;
                    float u11 = acc2[mt][nt][3] + bc1; u11 = (u11 >= 0.f) ? u11 : a2*u11;
                    pr[mt][0] = fmaf(u00, w0, fmaf(u01, w1, pr[mt][0]));
                    pr[mt][1] = fmaf(u10, w0, fmaf(u11, w1, pr[mt][1]));
                }
            }
            #pragma unroll
            for (int mt = 0; mt < 2; mt++) {
                #pragma unroll
                for (int rr = 0; rr < 2; rr++) {
                    pr[mt][rr] += __shfl_xor_sync(0xffffffffu, pr[mt][rr], 1);
                    pr[mt][rr] += __shfl_xor_sync(0xffffffffu, pr[mt][rr], 2);
                }
            }
            if (t == 0) {
                float* red = (float*)(sm + OF_RED);
                int nh = wid >> 2;
                #pragma unroll
                for (int mt = 0; mt < 2; mt++) {
                    int r = mblk + mt*16 + g;
                    red[r*2 + nh]     = pr[mt][0];
                    red[(r+8)*2 + nh] = pr[mt][1];
                }
            }
        }
        __syncthreads();

        /* ---- out ---- */
        if (tid < ETD) {
            const float* red = (const float*)(sm + OF_RED);
            int eg = e0 + tid;
            if (eg < NEDGE)
                out[(size_t)b * NEDGE + eg] = red[tid*2] + red[tid*2 + 1] + b3;
        }
        /* next staging writes absh/mulh/psz (disjoint from red);
           ordering vs red reads is enforced by the stage-end __syncthreads */
    }
}

/* ======================= host launcher ======================= */
extern "C" void kernel_launch(void* const* d_in, const int* in_sizes, int n_in,
                              void* d_out, int out_size) {
    (void)in_sizes; (void)n_in; (void)out_size;
    const float* nf    = (const float*)d_in[1];
    const float* sc    = (const float*)d_in[2];
    const float* smean = (const float*)d_in[3];
    const float* sstd  = (const float*)d_in[4];
    const float* We1   = (const float*)d_in[5];
    const float* be1   = (const float*)d_in[6];
    const float* ae1   = (const float*)d_in[7];
    const float* We2   = (const float*)d_in[8];
    const float* be2   = (const float*)d_in[9];
    const float* ae2   = (const float*)d_in[10];
    const float* Wd1   = (const float*)d_in[11];
    const float* bd1   = (const float*)d_in[12];
    const float* ad1   = (const float*)d_in[13];
    const float* Wd2   = (const float*)d_in[14];
    const float* bd2   = (const float*)d_in[15];
    const float* ad2   = (const float*)d_in[16];
    const float* Wd3   = (const float*)d_in[17];
    const float* bd3   = (const float*)d_in[18];
    const int*   ei    = (const int*)d_in[19];
    const int*   ej    = (const int*)d_in[20];
    float* out = (float*)d_out;

    float *pfeats, *ph1, *ph, *ppa;
    cudaGetSymbolAddress((void**)&pfeats, g_feats);
    cudaGetSymbolAddress((void**)&ph1,   g_h1);
    cudaGetSymbolAddress((void**)&ph,    g_h);
    cudaGetSymbolAddress((void**)&ppa,   g_Pa);

    cudaFuncSetAttribute(decoder_mma_kernel,
                         cudaFuncAttributeMaxDynamicSharedMemorySize, DEC_SMEM);

    reduce_mean_kernel<<<BATCH, 256>>>(sc);
    build_feats_kernel<<<(NROWS*FEATDIM + 255)/256, 256>>>(nf, sc, smean, sstd);
    gemm_kernel<<<dim3(NROWS/64, 2), 256>>>(pfeats, We1, be1, ae1, ph1, NROWS, FEATDIM, HIDDIM);
    gemm_kernel<<<dim3(NROWS/64, 2), 256>>>(ph1, We2, be2, ae2, ph, NROWS, HIDDIM, HIDDIM);
    gemm_kernel<<<dim3(NROWS/64, 1), 256>>>(ph, Wd1, nullptr, nullptr, ppa, NROWS, HIDDIM, DECDIM);
    decoder_mma_kernel<<<NCTA_DEC, 256, DEC_SMEM>>>(
        ph, ppa, Wd1, bd1, ad1, Wd2, bd2, ad2, Wd3, bd3, ei, ej, out);
}

// round 11
// speedup vs baseline: 4.9451x; 1.0855x over previous
#include <cuda_runtime.h>
#include <cuda_fp16.h>
#include <cstdint>

#define BATCH   16
#define NN      400
#define HIDDIM  96
#define DECDIM  64
#define NEDGE   79800
#define NROWS   (BATCH*NN)      /* 6400 */
#define FEATDIM 408
#define EPSF    1e-8f

#define ETD     128             /* edges per CTA tile (4 pair-slabs of 32) */
#define NTILE   624             /* ceil(79800/128) */
#define NWORK   (NTILE*BATCH)   /* 9984 */
#define NCTA_DEC 296            /* 2 CTAs per SM */

/* strides: k=96 A arrays padded to 104 halves (208B rows, conflict-free ldmatrix
   perm 20*g mod 32); k=64 z array 72 halves (144B, perm 4*g). */
#define AKW   52
#define ZKW   36

/* ---- smem byte offsets (total 110336 B -> 2 CTAs/SM) ---- */
#define OF_ABSH 0               /* 128x104 f16 = 26624 */
#define OF_MULH 26624
#define OF_WBH  53248           /* 64x104 f16 = 13312 */
#define OF_WCH  66560
#define OF_W2H  79872           /* 64x72 f16 = 9216 */
#define OF_B1   89088
#define OF_B2   89344
#define OF_W3   89600
#define OF_Z1H  89856           /* 128x72 f16 = 18432 */
#define OF_RED  108288          /* 128x2 f32 = 1024 */
#define OF_EI   109312          /* 128 int */
#define OF_EJ   109824
#define DEC_SMEM 110336

/* -------- scratch (device globals; no runtime allocation allowed) -------- */
__device__ float g_inv[BATCH];
__device__ float g_h1[NROWS*HIDDIM];
__device__ float g_h[NROWS*HIDDIM];
__device__ float g_Pa[NROWS*DECDIM];

/* ======================= helpers ======================= */
__device__ __forceinline__ uint32_t smem_u32(const void* p) {
    uint32_t a;
    asm("{ .reg .u64 t; cvta.to.shared.u64 t, %1; cvt.u32.u64 %0, t; }" : "=r"(a) : "l"(p));
    return a;
}
__device__ __forceinline__ uint32_t packh2(float x0, float x1) {
    __half2 hh = __floats2half2_rn(x0, x1);
    return *reinterpret_cast<uint32_t*>(&hh);
}
__device__ __forceinline__ void ldsm4(uint32_t* r, uint32_t a) {
    asm volatile("ldmatrix.sync.aligned.m8n8.x4.shared.b16 {%0,%1,%2,%3}, [%4];"
                 : "=r"(r[0]), "=r"(r[1]), "=r"(r[2]), "=r"(r[3]) : "r"(a));
}
__device__ __forceinline__ void mma_f16(float* c, const uint32_t* a, uint32_t b0, uint32_t b1) {
    asm volatile("mma.sync.aligned.m16n8k16.row.col.f32.f16.f16.f32 "
                 "{%0,%1,%2,%3}, {%4,%5,%6,%7}, {%8,%9}, {%0,%1,%2,%3};"
                 : "+f"(c[0]), "+f"(c[1]), "+f"(c[2]), "+f"(c[3])
                 : "r"(a[0]), "r"(a[1]), "r"(a[2]), "r"(a[3]), "r"(b0), "r"(b1));
}
/* 64-thread pair barrier (named; ids 1..4, distinct per warp pair within CTA) */
#define PBAR(id) asm volatile("bar.sync %0, 64;" :: "r"(id) : "memory")

/* ======================= encoder kernels ======================= */
__global__ void reduce_mean_kernel(const float* __restrict__ sc) {
    __shared__ float red[256];
    int b = blockIdx.x;
    const float* p = sc + (size_t)b * NN * NN;
    float s = 0.f;
    for (int i = threadIdx.x; i < NN*NN; i += 256) s += p[i];
    red[threadIdx.x] = s;
    __syncthreads();
    for (int st = 128; st > 0; st >>= 1) {
        if (threadIdx.x < st) red[threadIdx.x] += red[threadIdx.x + st];
        __syncthreads();
    }
    if (threadIdx.x == 0) g_inv[b] = 1.f / fmaxf(red[0] * (1.f/(float)(NN*NN)), EPSF);
}

/* encoder GEMM1 with A generated on the fly (feats never materialized) */
__global__ __launch_bounds__(256) void gemm_enc1_kernel(
    const float* __restrict__ nf, const float* __restrict__ sc,
    const float* __restrict__ smean, const float* __restrict__ sstd,
    const float* __restrict__ W, const float* __restrict__ bias,
    const float* __restrict__ alphap, float* __restrict__ C)
{
    __shared__ float As[8][64];
    __shared__ float Bs[8][64];
    int tid = threadIdx.x;
    int m0 = blockIdx.x * 64, n0 = blockIdx.y * 64;
    int ty = tid >> 4, tx = tid & 15;
    const int K = FEATDIM, N = HIDDIM;
    float acc[4][4] = {};
    for (int k0 = 0; k0 < K; k0 += 8) {
        #pragma unroll
        for (int i = tid; i < 512; i += 256) {
            int m = i >> 3, k = i & 7;
            int row = m0 + m, c = k0 + k;
            float v;
            if (c < 8) v = (nf[row*8 + c] - smean[c]) / (sstd[c] + EPSF);
            else       v = sc[(size_t)row*NN + (c-8)] * g_inv[row / NN];
            As[k][m] = v;
        }
        #pragma unroll
        for (int i = tid; i < 512; i += 256) {
            int k = i >> 6, n = i & 63;
            Bs[k][n] = (n0 + n < N) ? W[(size_t)(k0 + k) * N + (n0 + n)] : 0.f;
        }
        __syncthreads();
        #pragma unroll
        for (int kk = 0; kk < 8; kk++) {
            float4 a  = *(const float4*)&As[kk][ty*4];
            float4 bv = *(const float4*)&Bs[kk][tx*4];
            float av[4] = {a.x, a.y, a.z, a.w};
            float bw[4] = {bv.x, bv.y, bv.z, bv.w};
            #pragma unroll
            for (int i2 = 0; i2 < 4; i2++)
                #pragma unroll
                for (int j2 = 0; j2 < 4; j2++)
                    acc[i2][j2] = fmaf(av[i2], bw[j2], acc[i2][j2]);
        }
        __syncthreads();
    }
    float alpha = alphap[0];
    #pragma unroll
    for (int i2 = 0; i2 < 4; i2++) {
        int row = m0 + ty*4 + i2;
        #pragma unroll
        for (int j2 = 0; j2 < 4; j2++) {
            int col = n0 + tx*4 + j2;
            if (col < N) {
                float v = acc[i2][j2] + bias[col];
                v = (v >= 0.f) ? v : alpha * v;
                C[(size_t)row * N + col] = v;
            }
        }
    }
}

__global__ __launch_bounds__(256) void gemm_kernel(
    const float* __restrict__ A, const float* __restrict__ W,
    const float* __restrict__ bias, const float* __restrict__ alphap,
    float* __restrict__ C, int M, int K, int N)
{
    __shared__ float As[8][64];
    __shared__ float Bs[8][64];
    int tid = threadIdx.x;
    int m0 = blockIdx.x * 64, n0 = blockIdx.y * 64;
    int ty = tid >> 4, tx = tid & 15;
    float acc[4][4] = {};
    for (int k0 = 0; k0 < K; k0 += 8) {
        #pragma unroll
        for (int i = tid; i < 512; i += 256) {
            int m = i >> 3, k = i & 7;
            As[k][m] = A[(size_t)(m0 + m) * K + (k0 + k)];
        }
        #pragma unroll
        for (int i = tid; i < 512; i += 256) {
            int k = i >> 6, n = i & 63;
            Bs[k][n] = (n0 + n < N) ? W[(size_t)(k0 + k) * N + (n0 + n)] : 0.f;
        }
        __syncthreads();
        #pragma unroll
        for (int kk = 0; kk < 8; kk++) {
            float4 a  = *(const float4*)&As[kk][ty*4];
            float4 bv = *(const float4*)&Bs[kk][tx*4];
            float av[4] = {a.x, a.y, a.z, a.w};
            float bw[4] = {bv.x, bv.y, bv.z, bv.w};
            #pragma unroll
            for (int i2 = 0; i2 < 4; i2++)
                #pragma unroll
                for (int j2 = 0; j2 < 4; j2++)
                    acc[i2][j2] = fmaf(av[i2], bw[j2], acc[i2][j2]);
        }
        __syncthreads();
    }
    float alpha = alphap ? alphap[0] : 0.f;
    bool act = (alphap != nullptr);
    #pragma unroll
    for (int i2 = 0; i2 < 4; i2++) {
        int row = m0 + ty*4 + i2;
        #pragma unroll
        for (int j2 = 0; j2 < 4; j2++) {
            int col = n0 + tx*4 + j2;
            if (col < N) {
                float v = acc[i2][j2] + (bias ? bias[col] : 0.f);
                if (act) v = (v >= 0.f) ? v : alpha * v;
                C[(size_t)row * N + col] = v;
            }
        }
    }
}

/* ======= fp16 mma.sync persistent decoder: pairwise-independent pipelines ======= */
__global__ __launch_bounds__(256, 2)
void decoder_mma_kernel(
    const float* __restrict__ h, const float* __restrict__ Pa,
    const float* __restrict__ Wd1, const float* __restrict__ b1,
    const float* __restrict__ a1p, const float* __restrict__ W2,
    const float* __restrict__ b2, const float* __restrict__ a2p,
    const float* __restrict__ W3, const float* __restrict__ b3p,
    const int* __restrict__ ei, const int* __restrict__ ej,
    float* __restrict__ out)
{
    extern __shared__ char sm[];
    uint32_t smb = smem_u32(sm);
    int tid  = threadIdx.x;
    int wid  = tid >> 5;
    int lane = tid & 31;
    int g    = lane >> 2;
    int t    = lane & 3;
    int pair  = wid & 3;        /* slab index 0..3 */
    int half  = wid >> 2;       /* 0/1: n-half + staging sub-rows */
    int mblk  = pair * 32;
    int nhalf = half * 32;
    int barid = pair + 1;       /* named barriers 1..4 (0 = __syncthreads) */

    /* ---- stage weights once (single fp16, [n][k]) ---- */
    for (int idx = tid; idx < 64*96; idx += 256) {
        int n = idx / 96, k = idx - n * 96;
        int o = n * 104 + k;
        ((__half*)(sm + OF_WBH))[o] = __float2half_rn(Wd1[(96  + k)*64 + n]);
        ((__half*)(sm + OF_WCH))[o] = __float2half_rn(Wd1[(192 + k)*64 + n]);
    }
    for (int idx = tid; idx < 64*64; idx += 256) {
        int n = idx >> 6, k = idx & 63;
        ((__half*)(sm + OF_W2H))[n * 72 + k] = __float2half_rn(W2[k*64 + n]);
    }
    if (tid < 64) {
        ((float*)(sm + OF_B1))[tid] = b1[tid];
        ((float*)(sm + OF_B2))[tid] = b2[tid];
        ((float*)(sm + OF_W3))[tid] = W3[tid];
    }
    float a1 = a1p[0], a2 = a2p[0], b3 = b3p[0];
    __syncthreads();

    /* per-warp ldmatrix lane address components */
    uint32_t laneA  = (uint32_t)((lane & 15)*208 + (lane >> 4)*16);
    uint32_t laneB  = (uint32_t)(((lane >> 4)*8 + (lane & 7))*208 + ((lane >> 3) & 1)*16);
    uint32_t laneAz = (uint32_t)((lane & 15)*144 + (lane >> 4)*16);
    uint32_t laneBz = (uint32_t)(((lane >> 4)*8 + (lane & 7))*144 + ((lane >> 3) & 1)*16);

    uint32_t aAbs = smb + OF_ABSH + mblk*208 + laneA;
    uint32_t aMul = smb + OF_MULH + mblk*208 + laneA;
    uint32_t bWbh = smb + OF_WBH + nhalf*208 + laneB;
    uint32_t bWch = smb + OF_WCH + nhalf*208 + laneB;
    uint32_t aZh  = smb + OF_Z1H + mblk*144 + laneAz;
    uint32_t bW2h = smb + OF_W2H + nhalf*144 + laneBz;

    const int* s_ei = (const int*)(sm + OF_EI);
    const int* s_ej = (const int*)(sm + OF_EJ);

    for (int work = blockIdx.x; work < NWORK; work += NCTA_DEC) {
        int b  = work / NTILE;
        int tt = work - b * NTILE;
        int e0 = tt * ETD;

        /* ---- stage (pair-local): this warp stages rows rb..rb+15 of its slab ---- */
        {
            int rb = mblk + half*16;
            int myidx;
            {
                int e = e0 + rb + (lane & 15); if (e >= NEDGE) e = NEDGE - 1;
                myidx = (lane < 16) ? ei[e] : ej[e];
            }
            if (lane < 16) ((int*)(sm + OF_EI))[rb + lane] = myidx;
            else           ((int*)(sm + OF_EJ))[rb + lane - 16] = myidx;

            #pragma unroll 4
            for (int e = 0; e < 16; e++) {
                int ii = __shfl_sync(0xffffffffu, myidx, e);
                int jj = __shfl_sync(0xffffffffu, myidx, e + 16);
                if (lane < 24) {
                    const float4* hi4 = (const float4*)(h + ((size_t)b*NN + ii) * 96);
                    const float4* hj4 = (const float4*)(h + ((size_t)b*NN + jj) * 96);
                    float4 x = hi4[lane];
                    float4 y = hj4[lane];
                    uint2 aw = make_uint2(packh2(fabsf(x.x - y.x), fabsf(x.y - y.y)),
                                          packh2(fabsf(x.z - y.z), fabsf(x.w - y.w)));
                    uint2 mw = make_uint2(packh2(x.x*y.x, x.y*y.y), packh2(x.z*y.z, x.w*y.w));
                    int row = rb + e;
                    *(uint2*)(sm + OF_ABSH + (size_t)row*208 + lane*8) = aw;
                    *(uint2*)(sm + OF_MULH + (size_t)row*208 + lane*8) = mw;
                }
            }
        }
        PBAR(barid);

        /* ---- GEMM1: C1 = abs@Wb + mul@Wc (single fp16, fp32 acc) ---- */
        float acc[2][4][4];
        #pragma unroll
        for (int mt = 0; mt < 2; mt++)
            #pragma unroll
            for (int nt = 0; nt < 4; nt++)
                #pragma unroll
                for (int c = 0; c < 4; c++) acc[mt][nt][c] = 0.f;

        #pragma unroll
        for (int kc = 0; kc < 6; kc++) {
            uint32_t kb = kc * 32;
            uint32_t Aa[2][4], Am[2][4];
            ldsm4(Aa[0], aAbs + kb);
            ldsm4(Aa[1], aAbs + 16*208 + kb);
            ldsm4(Am[0], aMul + kb);
            ldsm4(Am[1], aMul + 16*208 + kb);
            uint32_t Bb[2][4], Bc[2][4];
            #pragma unroll
            for (int p = 0; p < 2; p++) {
                ldsm4(Bb[p], bWbh + p*16*208 + kb);
                ldsm4(Bc[p], bWch + p*16*208 + kb);
            }
            #pragma unroll
            for (int nt = 0; nt < 4; nt++) {
                int p = nt >> 1, q = (nt & 1) * 2;
                #pragma unroll
                for (int mt = 0; mt < 2; mt++) {
                    float* c = acc[mt][nt];
                    mma_f16(c, Aa[mt], Bb[p][q], Bb[p][q+1]);
                    mma_f16(c, Am[mt], Bc[p][q], Bc[p][q+1]);
                }
            }
        }

        /* ---- epilogue 1: z1 = prelu(C1 + (Pa_i+Pa_j) + b1) -> fp16 (Pa from L2) ---- */
        {
            const float* sb1 = (const float*)(sm + OF_B1);
            #pragma unroll
            for (int mt = 0; mt < 2; mt++) {
                int r = mblk + mt*16 + g;
                const float* pi0 = Pa + ((size_t)b*NN + s_ei[r]) * 64;
                const float* pj0 = Pa + ((size_t)b*NN + s_ej[r]) * 64;
                const float* pi1 = Pa + ((size_t)b*NN + s_ei[r+8]) * 64;
                const float* pj1 = Pa + ((size_t)b*NN + s_ej[r+8]) * 64;
                #pragma unroll
                for (int nt = 0; nt < 4; nt++) {
                    int c = nhalf + nt*8 + 2*t;
                    float2 A0 = *(const float2*)(pi0 + c);
                    float2 B0 = *(const float2*)(pj0 + c);
                    float2 A1 = *(const float2*)(pi1 + c);
                    float2 B1 = *(const float2*)(pj1 + c);
                    float bc0 = sb1[c], bc1 = sb1[c+1];
                    float u00 = acc[mt][nt][0] + A0.x + B0.x + bc0; u00 = (u00 >= 0.f) ? u00 : a1*u00;
                    float u01 = acc[mt][nt][1] + A0.y + B0.y + bc1; u01 = (u01 >= 0.f) ? u01 : a1*u01;
                    float u10 = acc[mt][nt][2] + A1.x + B1.x + bc0; u10 = (u10 >= 0.f) ? u10 : a1*u10;
                    float u11 = acc[mt][nt][3] + A1.y + B1.y + bc1; u11 = (u11 >= 0.f) ? u11 : a1*u11;
                    *(uint32_t*)(sm + OF_Z1H + (size_t)r*144 + c*2)     = packh2(u00, u01);
                    *(uint32_t*)(sm + OF_Z1H + (size_t)(r+8)*144 + c*2) = packh2(u10, u11);
                }
            }
        }
        PBAR(barid);

        /* ---- GEMM2: C2 = z1 @ W2 (single fp16) ---- */
        float acc2[2][4][4];
        #pragma unroll
        for (int mt = 0; mt < 2; mt++)
            #pragma unroll
            for (int nt = 0; nt < 4; nt++)
                #pragma unroll
                for (int c = 0; c < 4; c++) acc2[mt][nt][c] = 0.f;

        #pragma unroll
        for (int kc = 0; kc < 4; kc++) {
            uint32_t kb = kc * 32;
            uint32_t Zh[2][4];
            ldsm4(Zh[0], aZh + kb);
            ldsm4(Zh[1], aZh + 16*144 + kb);
            uint32_t B2[2][4];
            #pragma unroll
            for (int p = 0; p < 2; p++)
                ldsm4(B2[p], bW2h + p*16*144 + kb);
            #pragma unroll
            for (int nt = 0; nt < 4; nt++) {
                int p = nt >> 1, q = (nt & 1) * 2;
                #pragma unroll
                for (int mt = 0; mt < 2; mt++)
                    mma_f16(acc2[mt][nt], Zh[mt], B2[p][q], B2[p][q+1]);
            }
        }

        /* ---- epilogue 2: dot(prelu(C2 + b2), w3) -> red (pair slice) ---- */
        {
            const float* sb2 = (const float*)(sm + OF_B2);
            const float* sw3 = (const float*)(sm + OF_W3);
            float pr[2][2] = {{0.f,0.f},{0.f,0.f}};
            #pragma unroll
            for (int mt = 0; mt < 2; mt++) {
                #pragma unroll
                for (int nt = 0; nt < 4; nt++) {
                    int c = nhalf + nt*8 + 2*t;
                    float bc0 = sb2[c], bc1 = sb2[c+1];
                    float w0 = sw3[c],  w1 = sw3[c+1];
                    float u00 = acc2[mt][nt][0] + bc0; u00 = (u00 >= 0.f) ? u00 : a2*u00;
                    float u01 = acc2[mt][nt][1] + bc1; u01 = (u01 >= 0.f) ? u01 : a2*u01;
                    float u10 = acc2[mt][nt][2] + bc0; u10 = (u10 >= 0.f) ? u10 : a2*u10;
                    float u11 = acc2[mt][nt][3] + bc1; u11 = (u11 >= 0.f) ? u11 : a2*u11;
                    pr[mt][0] = fmaf(u00, w0, fmaf(u01, w1, pr[mt][0]));
                    pr[mt][1] = fmaf(u10, w0, fmaf(u11, w1, pr[mt][1]));
                }
            }
            #pragma unroll
            for (int mt = 0; mt < 2; mt++) {
                #pragma unroll
                for (int rr = 0; rr < 2; rr++) {
                    pr[mt][rr] += __shfl_xor_sync(0xffffffffu, pr[mt][rr], 1);
                    pr[mt][rr] += __shfl_xor_sync(0xffffffffu, pr[mt][rr], 2);
                }
            }
            if (t == 0) {
                float* red = (float*)(sm + OF_RED);
                #pragma unroll
                for (int mt = 0; mt < 2; mt++) {
                    int r = mblk + mt*16 + g;
                    red[r*2 + half]     = pr[mt][0];
                    red[(r+8)*2 + half] = pr[mt][1];
                }
            }
        }
        PBAR(barid);

        /* ---- out: warp q writes its slab's 32 edges ---- */
        if (half == 0) {
            const float* red = (const float*)(sm + OF_RED);
            int r  = mblk + lane;
            int eg = e0 + r;
            if (eg < NEDGE)
                out[(size_t)b * NEDGE + eg] = red[r*2] + red[r*2 + 1] + b3;
        }
        /* pair-local ordering of next-tile smem reuse is enforced by the
           pair barriers of the next iteration (both warps participate) */
    }
}

/* ======================= host launcher ======================= */
extern "C" void kernel_launch(void* const* d_in, const int* in_sizes, int n_in,
                              void* d_out, int out_size) {
    (void)in_sizes; (void)n_in; (void)out_size;
    const float* nf    = (const float*)d_in[1];
    const float* sc    = (const float*)d_in[2];
    const float* smean = (const float*)d_in[3];
    const float* sstd  = (const float*)d_in[4];
    const float* We1   = (const float*)d_in[5];
    const float* be1   = (const float*)d_in[6];
    const float* ae1   = (const float*)d_in[7];
    const float* We2   = (const float*)d_in[8];
    const float* be2   = (const float*)d_in[9];
    const float* ae2   = (const float*)d_in[10];
    const float* Wd1   = (const float*)d_in[11];
    const float* bd1   = (const float*)d_in[12];
    const float* ad1   = (const float*)d_in[13];
    const float* Wd2   = (const float*)d_in[14];
    const float* bd2   = (const float*)d_in[15];
    const float* ad2   = (const float*)d_in[16];
    const float* Wd3   = (const float*)d_in[17];
    const float* bd3   = (const float*)d_in[18];
    const int*   ei    = (const int*)d_in[19];
    const int*   ej    = (const int*)d_in[20];
    float* out = (float*)d_out;

    float *ph1, *ph, *ppa;
    cudaGetSymbolAddress((void**)&ph1, g_h1);
    cudaGetSymbolAddress((void**)&ph,  g_h);
    cudaGetSymbolAddress((void**)&ppa, g_Pa);

    cudaFuncSetAttribute(decoder_mma_kernel,
                         cudaFuncAttributeMaxDynamicSharedMemorySize, DEC_SMEM);

    reduce_mean_kernel<<<BATCH, 256>>>(sc);
    /* h1 = prelu(feats @ W_e1 + b_e1), feats generated on the fly */
    gemm_enc1_kernel<<<dim3(NROWS/64, 2), 256>>>(nf, sc, smean, sstd, We1, be1, ae1, ph1);
    gemm_kernel<<<dim3(NROWS/64, 2), 256>>>(ph1, We2, be2, ae2, ph, NROWS, HIDDIM, HIDDIM);
    gemm_kernel<<<dim3(NROWS/64, 1), 256>>>(ph, Wd1, nullptr, nullptr, ppa, NROWS, HIDDIM, DECDIM);
    decoder_mma_kernel<<<NCTA_DEC, 256, DEC_SMEM>>>(
        ph, ppa, Wd1, bd1, ad1, Wd2, bd2, ad2, Wd3, bd3, ei, ej, out);
}